// round 1
// baseline (speedup 1.0000x reference)
#include <cuda_runtime.h>
#include <math.h>

#define D_MODEL 1024
#define NH      16
#define DH      64
#define BATCH   2
#define SEQ     2048
#define NTOK    (BATCH * SEQ)   // 4096

// Scratch (device globals — no runtime allocation allowed)
__device__ float g_q[NTOK * D_MODEL];
__device__ float g_k[NTOK * D_MODEL];
__device__ float g_v[NTOK * D_MODEL];
__device__ float g_ctx[NTOK * D_MODEL];

// ---------------------------------------------------------------------------
// SGEMM: C[M,N] = A[M,K] @ W[N,K]^T    (both row-major, K contiguous)
// Tile 128x128, BK=16, 256 threads, 8x8 per thread.
// ---------------------------------------------------------------------------
__global__ __launch_bounds__(256) void sgemm_nt(
    const float* __restrict__ A, const float* __restrict__ W,
    float* __restrict__ C, int M, int N, int K)
{
    __shared__ float As[16][132];   // [k][m], padded to reduce transpose-store conflicts
    __shared__ float Bs[16][132];   // [k][n]

    const int tid = threadIdx.x;
    const int tx  = tid & 15;       // 0..15 -> n micro
    const int ty  = tid >> 4;       // 0..15 -> m micro
    const int bm  = blockIdx.y * 128;
    const int bn  = blockIdx.x * 128;

    float acc[8][8];
#pragma unroll
    for (int i = 0; i < 8; i++)
#pragma unroll
        for (int j = 0; j < 8; j++) acc[i][j] = 0.f;

    const float* Ap = A + (size_t)bm * K;
    const float* Wp = W + (size_t)bn * K;

    for (int k0 = 0; k0 < K; k0 += 16) {
#pragma unroll
        for (int i = 0; i < 2; i++) {
            int id  = tid * 2 + i;        // 0..511
            int row = id >> 2;            // 0..127
            int kc  = (id & 3) << 2;      // 0,4,8,12
            float4 va = *reinterpret_cast<const float4*>(Ap + (size_t)row * K + k0 + kc);
            As[kc + 0][row] = va.x; As[kc + 1][row] = va.y;
            As[kc + 2][row] = va.z; As[kc + 3][row] = va.w;
            float4 vb = *reinterpret_cast<const float4*>(Wp + (size_t)row * K + k0 + kc);
            Bs[kc + 0][row] = vb.x; Bs[kc + 1][row] = vb.y;
            Bs[kc + 2][row] = vb.z; Bs[kc + 3][row] = vb.w;
        }
        __syncthreads();

#pragma unroll
        for (int kk = 0; kk < 16; kk++) {
            float a[8], b[8];
            *reinterpret_cast<float4*>(&a[0]) = *reinterpret_cast<const float4*>(&As[kk][ty * 8]);
            *reinterpret_cast<float4*>(&a[4]) = *reinterpret_cast<const float4*>(&As[kk][ty * 8 + 4]);
            *reinterpret_cast<float4*>(&b[0]) = *reinterpret_cast<const float4*>(&Bs[kk][tx * 8]);
            *reinterpret_cast<float4*>(&b[4]) = *reinterpret_cast<const float4*>(&Bs[kk][tx * 8 + 4]);
#pragma unroll
            for (int i = 0; i < 8; i++)
#pragma unroll
                for (int j = 0; j < 8; j++)
                    acc[i][j] += a[i] * b[j];
        }
        __syncthreads();
    }

#pragma unroll
    for (int i = 0; i < 8; i++) {
        float* cp = C + (size_t)(bm + ty * 8 + i) * N + bn + tx * 8;
        float4 v0 = make_float4(acc[i][0], acc[i][1], acc[i][2], acc[i][3]);
        float4 v1 = make_float4(acc[i][4], acc[i][5], acc[i][6], acc[i][7]);
        *reinterpret_cast<float4*>(cp)     = v0;
        *reinterpret_cast<float4*>(cp + 4) = v1;
    }
}

// ---------------------------------------------------------------------------
// Causal flash attention, fp32.
// Q/K/V layout: [B*S, D_MODEL] row-major (head h occupies cols h*64..h*64+63).
// One block per (q-tile of 64, head, batch). 256 threads: 16x16, each thread
// owns a 4(row) x 4(col) micro-tile of the 64x64 score / output tiles.
// smem: Qs[64][64] natural, KP[64][64] (K^T with XOR swizzle, reused for P),
//       Vs[64][64] natural -> exactly 48 KB static.
// ---------------------------------------------------------------------------
__global__ __launch_bounds__(256) void attn_kernel(
    const float* __restrict__ Q, const float* __restrict__ K,
    const float* __restrict__ V, float* __restrict__ O)
{
    __shared__ float Qs[64 * 64];   // [r][d]
    __shared__ float KP[64 * 64];   // K^T: [d][c ^ d]; later P: [r][c]
    __shared__ float Vs[64 * 64];   // [c][d]

    const int tid = threadIdx.x;
    const int tx  = tid & 15;
    const int ty  = tid >> 4;
    const int qt  = blockIdx.x;
    const int h   = blockIdx.y;
    const int b   = blockIdx.z;
    const int q0  = qt * 64;
    const size_t hb = (size_t)b * SEQ * D_MODEL + (size_t)h * DH;

    // Load Q tile (natural layout), 4 float4 per thread
#pragma unroll
    for (int i = 0; i < 4; i++) {
        int id = tid + 256 * i;            // 0..1023
        int r  = id >> 4;
        int d0 = (id & 15) * 4;
        float4 v = *reinterpret_cast<const float4*>(Q + hb + (size_t)(q0 + r) * D_MODEL + d0);
        *reinterpret_cast<float4*>(&Qs[r * 64 + d0]) = v;
    }

    const int r0 = ty * 4;
    const int c0 = tx * 4;

    float m_i[4], l_i[4], acc[4][4];
#pragma unroll
    for (int i = 0; i < 4; i++) {
        m_i[i] = -INFINITY; l_i[i] = 0.f;
#pragma unroll
        for (int j = 0; j < 4; j++) acc[i][j] = 0.f;
    }

    for (int kt = 0; kt <= qt; kt++) {
        const int k0 = kt * 64;
        __syncthreads();   // prior P/V reads (and Q stores on iter 0) complete

        // Load K tile transposed with XOR swizzle, V tile natural
#pragma unroll
        for (int i = 0; i < 4; i++) {
            int id = tid + 256 * i;
            int c  = id >> 4;
            int d0 = (id & 15) * 4;
            float4 kv = *reinterpret_cast<const float4*>(K + hb + (size_t)(k0 + c) * D_MODEL + d0);
            KP[(d0 + 0) * 64 + (c ^ (d0 + 0))] = kv.x;
            KP[(d0 + 1) * 64 + (c ^ (d0 + 1))] = kv.y;
            KP[(d0 + 2) * 64 + (c ^ (d0 + 2))] = kv.z;
            KP[(d0 + 3) * 64 + (c ^ (d0 + 3))] = kv.w;
            float4 vv = *reinterpret_cast<const float4*>(V + hb + (size_t)(k0 + c) * D_MODEL + d0);
            *reinterpret_cast<float4*>(&Vs[c * 64 + d0]) = vv;
        }
        __syncthreads();

        // Scores: s[i][j] = Q[r0+i,:] . K[c0+j,:]
        float s[4][4];
#pragma unroll
        for (int i = 0; i < 4; i++)
#pragma unroll
            for (int j = 0; j < 4; j++) s[i][j] = 0.f;

#pragma unroll 8
        for (int kk = 0; kk < 64; kk++) {
            float qf[4], kf[4];
#pragma unroll
            for (int i = 0; i < 4; i++) qf[i] = Qs[(r0 + i) * 64 + kk];
#pragma unroll
            for (int j = 0; j < 4; j++) kf[j] = KP[kk * 64 + ((c0 + j) ^ kk)];
#pragma unroll
            for (int i = 0; i < 4; i++)
#pragma unroll
                for (int j = 0; j < 4; j++)
                    s[i][j] += qf[i] * kf[j];
        }

        const float scale = 0.125f;     // 1/sqrt(64)
        const bool diag = (kt == qt);
#pragma unroll
        for (int i = 0; i < 4; i++)
#pragma unroll
            for (int j = 0; j < 4; j++) {
                float v = s[i][j] * scale;
                if (diag && (c0 + j > r0 + i)) v = -INFINITY;
                s[i][j] = v;
            }

        // Online softmax: row max (width-16 shuffle across tx)
        float m_new[4], alpha[4], p[4][4], rs[4];
#pragma unroll
        for (int i = 0; i < 4; i++) {
            float mt = fmaxf(fmaxf(s[i][0], s[i][1]), fmaxf(s[i][2], s[i][3]));
#pragma unroll
            for (int off = 8; off >= 1; off >>= 1)
                mt = fmaxf(mt, __shfl_xor_sync(0xffffffffu, mt, off, 16));
            m_new[i] = fmaxf(m_i[i], mt);
            alpha[i] = __expf(m_i[i] - m_new[i]);   // exp(-inf)=0 on first tile
            float r = 0.f;
#pragma unroll
            for (int j = 0; j < 4; j++) {
                p[i][j] = __expf(s[i][j] - m_new[i]);
                r += p[i][j];
            }
#pragma unroll
            for (int off = 8; off >= 1; off >>= 1)
                r += __shfl_xor_sync(0xffffffffu, r, off, 16);
            rs[i] = r;
        }
#pragma unroll
        for (int i = 0; i < 4; i++) {
            l_i[i] = l_i[i] * alpha[i] + rs[i];
            m_i[i] = m_new[i];
#pragma unroll
            for (int j = 0; j < 4; j++) acc[i][j] *= alpha[i];
        }

        __syncthreads();   // done reading KP as K^T
        // Stash P into KP as [r][c]
#pragma unroll
        for (int i = 0; i < 4; i++)
#pragma unroll
            for (int j = 0; j < 4; j++)
                KP[(r0 + i) * 64 + c0 + j] = p[i][j];
        __syncthreads();

        // acc += P @ V
#pragma unroll 8
        for (int c = 0; c < 64; c++) {
            float pf[4], vf[4];
#pragma unroll
            for (int i = 0; i < 4; i++) pf[i] = KP[(r0 + i) * 64 + c];
#pragma unroll
            for (int j = 0; j < 4; j++) vf[j] = Vs[c * 64 + c0 + j];
#pragma unroll
            for (int i = 0; i < 4; i++)
#pragma unroll
                for (int j = 0; j < 4; j++)
                    acc[i][j] += pf[i] * vf[j];
        }
    }

    // Epilogue: normalize and write ctx in [B*S, D_MODEL] layout
#pragma unroll
    for (int i = 0; i < 4; i++) {
        float inv = 1.f / l_i[i];
        float* op = O + (size_t)(b * SEQ + q0 + r0 + i) * D_MODEL + (size_t)h * DH + c0;
        float4 v = make_float4(acc[i][0] * inv, acc[i][1] * inv,
                               acc[i][2] * inv, acc[i][3] * inv);
        *reinterpret_cast<float4*>(op) = v;
    }
}

// ---------------------------------------------------------------------------
extern "C" void kernel_launch(void* const* d_in, const int* in_sizes, int n_in,
                              void* d_out, int out_size)
{
    const float* x  = (const float*)d_in[0];
    const float* Wq = (const float*)d_in[1];
    const float* Wk = (const float*)d_in[2];
    const float* Wv = (const float*)d_in[3];
    const float* Wo = (const float*)d_in[4];
    float* out = (float*)d_out;

    float *q, *k, *v, *ctx;
    cudaGetSymbolAddress((void**)&q,   g_q);
    cudaGetSymbolAddress((void**)&k,   g_k);
    cudaGetSymbolAddress((void**)&v,   g_v);
    cudaGetSymbolAddress((void**)&ctx, g_ctx);

    dim3 gg(D_MODEL / 128, NTOK / 128);   // (8, 32)
    sgemm_nt<<<gg, 256>>>(x, Wq, q, NTOK, D_MODEL, D_MODEL);
    sgemm_nt<<<gg, 256>>>(x, Wk, k, NTOK, D_MODEL, D_MODEL);
    sgemm_nt<<<gg, 256>>>(x, Wv, v, NTOK, D_MODEL, D_MODEL);

    attn_kernel<<<dim3(SEQ / 64, NH, BATCH), 256>>>(q, k, v, ctx);

    sgemm_nt<<<gg, 256>>>(ctx, Wo, out, NTOK, D_MODEL, D_MODEL);
}

// round 3
// speedup vs baseline: 1.6318x; 1.6318x over previous
#include <cuda_runtime.h>
#include <math.h>
#include <stdint.h>

#define D_MODEL 1024
#define NH      16
#define DH      64
#define BATCH   2
#define SEQ     2048
#define NTOK    (BATCH * SEQ)   // 4096

// Scratch (device globals — no runtime allocation allowed)
__device__ float g_q[NTOK * D_MODEL];
__device__ float g_k[NTOK * D_MODEL];
__device__ float g_v[NTOK * D_MODEL];
__device__ float g_ctx[NTOK * D_MODEL];

__device__ __forceinline__ uint32_t smem_u32(const void* p) {
    uint32_t a;
    asm("{ .reg .u64 t; cvta.to.shared.u64 t, %1; cvt.u32.u64 %0, t; }" : "=r"(a) : "l"(p));
    return a;
}

// ============================================================================
// TF32 tensor-core GEMM via mma.sync (sm_80+ PTX, works on compute_103):
//   C[M,N] = A[M,K] @ W[N,K]^T   (row-major, K contiguous for both)
// CTA 128x128x32, 256 threads = 8 warps (2 x 4), warp tile 64x32.
// cp.async double buffer; ldmatrix fragment loads; cvt.rna.tf32 rounding.
// ============================================================================
#define BM 128
#define BN 128
#define BK 32
#define KSTR 36                      // smem row stride in floats (32 + 4 pad)
#define TILE_F (BM * KSTR)           // floats per operand tile
#define SMEM_FLOATS (4 * TILE_F)     // A0,A1,B0,B1
#define SMEM_BYTES (SMEM_FLOATS * 4) // 73728

__device__ __forceinline__ void ldsm_x4(uint32_t (&r)[4], uint32_t addr) {
    asm volatile("ldmatrix.sync.aligned.m8n8.x4.shared.b16 {%0,%1,%2,%3}, [%4];"
                 : "=r"(r[0]), "=r"(r[1]), "=r"(r[2]), "=r"(r[3]) : "r"(addr));
}
__device__ __forceinline__ void cvt_tf32(uint32_t& x) {
    asm volatile("cvt.rna.tf32.f32 %0, %0;" : "+r"(x));
}
__device__ __forceinline__ void mma_tf32(float (&c)[4], const uint32_t a[4],
                                         uint32_t b0, uint32_t b1) {
    asm volatile(
        "mma.sync.aligned.m16n8k8.row.col.f32.tf32.tf32.f32 "
        "{%0,%1,%2,%3}, {%4,%5,%6,%7}, {%8,%9}, {%0,%1,%2,%3};"
        : "+f"(c[0]), "+f"(c[1]), "+f"(c[2]), "+f"(c[3])
        : "r"(a[0]), "r"(a[1]), "r"(a[2]), "r"(a[3]), "r"(b0), "r"(b1));
}

__global__ __launch_bounds__(256) void sgemm_mma(
    const float* __restrict__ A, const float* __restrict__ W,
    float* __restrict__ C, int M, int N, int K)
{
    extern __shared__ float sm[];
    float* AsP[2] = { sm,             sm + TILE_F };
    float* BsP[2] = { sm + 2 * TILE_F, sm + 3 * TILE_F };

    const int tid  = threadIdx.x;
    const int wid  = tid >> 5;
    const int lane = tid & 31;
    const int bm   = blockIdx.y * BM;
    const int bn   = blockIdx.x * BN;

    const int wm = (wid >> 2) * 64;   // warp M offset within CTA tile
    const int wn = (wid & 3) * 32;    // warp N offset

    float acc[4][4][4];
#pragma unroll
    for (int i = 0; i < 4; i++)
#pragma unroll
        for (int j = 0; j < 4; j++)
#pragma unroll
            for (int q = 0; q < 4; q++) acc[i][j][q] = 0.f;

    // ldmatrix per-lane row addressing
    const int aj = lane >> 3;
    const int arow = ((aj & 1) << 3) + (lane & 7);
    const int acol = (aj >> 1) << 2;          // word col 0 or 4
    const int brow = ((aj >> 1) << 3) + (lane & 7);
    const int bcol = (aj & 1) << 2;

    uint32_t aAddr[2][4], bAddr[2][2];
#pragma unroll
    for (int buf = 0; buf < 2; buf++) {
#pragma unroll
        for (int mt = 0; mt < 4; mt++)
            aAddr[buf][mt] = smem_u32(AsP[buf] + (wm + mt * 16 + arow) * KSTR + acol);
#pragma unroll
        for (int p = 0; p < 2; p++)
            bAddr[buf][p] = smem_u32(BsP[buf] + (wn + p * 16 + brow) * KSTR + bcol);
    }

    const float* Ap = A + (size_t)bm * K;
    const float* Wp = W + (size_t)bn * K;

    const int KT = K / BK;   // 32

    // --- async tile loader: 4 x 16B chunks per thread per operand ---
    auto load_tile = [&](int t, int buf) {
        const float* Ag = Ap + t * BK;
        const float* Bg = Wp + t * BK;
        uint32_t sa = smem_u32(AsP[buf]);
        uint32_t sb = smem_u32(BsP[buf]);
#pragma unroll
        for (int i = 0; i < 4; i++) {
            int chunk = tid + 256 * i;       // 0..1023
            int row = chunk >> 3;
            int c   = chunk & 7;
            uint32_t so = (uint32_t)(row * KSTR + c * 4) * 4u;
            uint64_t ga = __cvta_generic_to_global(Ag + (size_t)row * K + c * 4);
            uint64_t gb = __cvta_generic_to_global(Bg + (size_t)row * K + c * 4);
            asm volatile("cp.async.cg.shared.global [%0], [%1], 16;" :: "r"(sa + so), "l"(ga) : "memory");
            asm volatile("cp.async.cg.shared.global [%0], [%1], 16;" :: "r"(sb + so), "l"(gb) : "memory");
        }
        asm volatile("cp.async.commit_group;" ::: "memory");
    };

    load_tile(0, 0);

    for (int t = 0; t < KT; t++) {
        const int buf = t & 1;
        if (t + 1 < KT) {
            load_tile(t + 1, buf ^ 1);
            asm volatile("cp.async.wait_group 1;" ::: "memory");
        } else {
            asm volatile("cp.async.wait_group 0;" ::: "memory");
        }
        __syncthreads();

#pragma unroll
        for (int ks = 0; ks < 4; ks++) {
            uint32_t afr[4][4], bfr[2][4];
#pragma unroll
            for (int mt = 0; mt < 4; mt++)
                ldsm_x4(afr[mt], aAddr[buf][mt] + ks * 32);
#pragma unroll
            for (int p = 0; p < 2; p++)
                ldsm_x4(bfr[p], bAddr[buf][p] + ks * 32);
#pragma unroll
            for (int mt = 0; mt < 4; mt++)
#pragma unroll
                for (int q = 0; q < 4; q++) cvt_tf32(afr[mt][q]);
#pragma unroll
            for (int p = 0; p < 2; p++)
#pragma unroll
                for (int q = 0; q < 4; q++) cvt_tf32(bfr[p][q]);

#pragma unroll
            for (int mt = 0; mt < 4; mt++)
#pragma unroll
                for (int nt = 0; nt < 4; nt++)
                    mma_tf32(acc[mt][nt], afr[mt], bfr[nt >> 1][(nt & 1) * 2],
                             bfr[nt >> 1][(nt & 1) * 2 + 1]);
        }
        __syncthreads();
    }

    // Epilogue: c0,c1 at (row, col..col+1); c2,c3 at (row+8, ...)
    const int rr = lane >> 2;
    const int cc = (lane & 3) * 2;
#pragma unroll
    for (int mt = 0; mt < 4; mt++) {
#pragma unroll
        for (int nt = 0; nt < 4; nt++) {
            int row = bm + wm + mt * 16 + rr;
            int col = bn + wn + nt * 8 + cc;
            float2 v01 = make_float2(acc[mt][nt][0], acc[mt][nt][1]);
            float2 v23 = make_float2(acc[mt][nt][2], acc[mt][nt][3]);
            *reinterpret_cast<float2*>(C + (size_t)row * N + col)       = v01;
            *reinterpret_cast<float2*>(C + (size_t)(row + 8) * N + col) = v23;
        }
    }
}

// ---------------------------------------------------------------------------
// Causal flash attention, fp32 (unchanged from R1 — 811us, next round's target)
// ---------------------------------------------------------------------------
__global__ __launch_bounds__(256) void attn_kernel(
    const float* __restrict__ Q, const float* __restrict__ K,
    const float* __restrict__ V, float* __restrict__ O)
{
    __shared__ float Qs[64 * 64];
    __shared__ float KP[64 * 64];
    __shared__ float Vs[64 * 64];

    const int tid = threadIdx.x;
    const int tx  = tid & 15;
    const int ty  = tid >> 4;
    const int qt  = blockIdx.x;
    const int h   = blockIdx.y;
    const int b   = blockIdx.z;
    const int q0  = qt * 64;
    const size_t hb = (size_t)b * SEQ * D_MODEL + (size_t)h * DH;

#pragma unroll
    for (int i = 0; i < 4; i++) {
        int id = tid + 256 * i;
        int r  = id >> 4;
        int d0 = (id & 15) * 4;
        float4 v = *reinterpret_cast<const float4*>(Q + hb + (size_t)(q0 + r) * D_MODEL + d0);
        *reinterpret_cast<float4*>(&Qs[r * 64 + d0]) = v;
    }

    const int r0 = ty * 4;
    const int c0 = tx * 4;

    float m_i[4], l_i[4], acc[4][4];
#pragma unroll
    for (int i = 0; i < 4; i++) {
        m_i[i] = -INFINITY; l_i[i] = 0.f;
#pragma unroll
        for (int j = 0; j < 4; j++) acc[i][j] = 0.f;
    }

    for (int kt = 0; kt <= qt; kt++) {
        const int k0 = kt * 64;
        __syncthreads();

#pragma unroll
        for (int i = 0; i < 4; i++) {
            int id = tid + 256 * i;
            int c  = id >> 4;
            int d0 = (id & 15) * 4;
            float4 kv = *reinterpret_cast<const float4*>(K + hb + (size_t)(k0 + c) * D_MODEL + d0);
            KP[(d0 + 0) * 64 + (c ^ (d0 + 0))] = kv.x;
            KP[(d0 + 1) * 64 + (c ^ (d0 + 1))] = kv.y;
            KP[(d0 + 2) * 64 + (c ^ (d0 + 2))] = kv.z;
            KP[(d0 + 3) * 64 + (c ^ (d0 + 3))] = kv.w;
            float4 vv = *reinterpret_cast<const float4*>(V + hb + (size_t)(k0 + c) * D_MODEL + d0);
            *reinterpret_cast<float4*>(&Vs[c * 64 + d0]) = vv;
        }
        __syncthreads();

        float s[4][4];
#pragma unroll
        for (int i = 0; i < 4; i++)
#pragma unroll
            for (int j = 0; j < 4; j++) s[i][j] = 0.f;

#pragma unroll 8
        for (int kk = 0; kk < 64; kk++) {
            float qf[4], kf[4];
#pragma unroll
            for (int i = 0; i < 4; i++) qf[i] = Qs[(r0 + i) * 64 + kk];
#pragma unroll
            for (int j = 0; j < 4; j++) kf[j] = KP[kk * 64 + ((c0 + j) ^ kk)];
#pragma unroll
            for (int i = 0; i < 4; i++)
#pragma unroll
                for (int j = 0; j < 4; j++)
                    s[i][j] += qf[i] * kf[j];
        }

        const float scale = 0.125f;
        const bool diag = (kt == qt);
#pragma unroll
        for (int i = 0; i < 4; i++)
#pragma unroll
            for (int j = 0; j < 4; j++) {
                float v = s[i][j] * scale;
                if (diag && (c0 + j > r0 + i)) v = -INFINITY;
                s[i][j] = v;
            }

        float m_new[4], alpha[4], p[4][4], rs[4];
#pragma unroll
        for (int i = 0; i < 4; i++) {
            float mt = fmaxf(fmaxf(s[i][0], s[i][1]), fmaxf(s[i][2], s[i][3]));
#pragma unroll
            for (int off = 8; off >= 1; off >>= 1)
                mt = fmaxf(mt, __shfl_xor_sync(0xffffffffu, mt, off, 16));
            m_new[i] = fmaxf(m_i[i], mt);
            alpha[i] = __expf(m_i[i] - m_new[i]);
            float r = 0.f;
#pragma unroll
            for (int j = 0; j < 4; j++) {
                p[i][j] = __expf(s[i][j] - m_new[i]);
                r += p[i][j];
            }
#pragma unroll
            for (int off = 8; off >= 1; off >>= 1)
                r += __shfl_xor_sync(0xffffffffu, r, off, 16);
            rs[i] = r;
        }
#pragma unroll
        for (int i = 0; i < 4; i++) {
            l_i[i] = l_i[i] * alpha[i] + rs[i];
            m_i[i] = m_new[i];
#pragma unroll
            for (int j = 0; j < 4; j++) acc[i][j] *= alpha[i];
        }

        __syncthreads();
#pragma unroll
        for (int i = 0; i < 4; i++)
#pragma unroll
            for (int j = 0; j < 4; j++)
                KP[(r0 + i) * 64 + c0 + j] = p[i][j];
        __syncthreads();

#pragma unroll 8
        for (int c = 0; c < 64; c++) {
            float pf[4], vf[4];
#pragma unroll
            for (int i = 0; i < 4; i++) pf[i] = KP[(r0 + i) * 64 + c];
#pragma unroll
            for (int j = 0; j < 4; j++) vf[j] = Vs[c * 64 + c0 + j];
#pragma unroll
            for (int i = 0; i < 4; i++)
#pragma unroll
                for (int j = 0; j < 4; j++)
                    acc[i][j] += pf[i] * vf[j];
        }
    }

#pragma unroll
    for (int i = 0; i < 4; i++) {
        float inv = 1.f / l_i[i];
        float* op = O + (size_t)(b * SEQ + q0 + r0 + i) * D_MODEL + (size_t)h * DH + c0;
        float4 v = make_float4(acc[i][0] * inv, acc[i][1] * inv,
                               acc[i][2] * inv, acc[i][3] * inv);
        *reinterpret_cast<float4*>(op) = v;
    }
}

// ---------------------------------------------------------------------------
extern "C" void kernel_launch(void* const* d_in, const int* in_sizes, int n_in,
                              void* d_out, int out_size)
{
    const float* x  = (const float*)d_in[0];
    const float* Wq = (const float*)d_in[1];
    const float* Wk = (const float*)d_in[2];
    const float* Wv = (const float*)d_in[3];
    const float* Wo = (const float*)d_in[4];
    float* out = (float*)d_out;

    float *q, *k, *v, *ctx;
    cudaGetSymbolAddress((void**)&q,   g_q);
    cudaGetSymbolAddress((void**)&k,   g_k);
    cudaGetSymbolAddress((void**)&v,   g_v);
    cudaGetSymbolAddress((void**)&ctx, g_ctx);

    cudaFuncSetAttribute(sgemm_mma, cudaFuncAttributeMaxDynamicSharedMemorySize, SMEM_BYTES);

    dim3 gg(D_MODEL / BN, NTOK / BM);   // (8, 32)
    sgemm_mma<<<gg, 256, SMEM_BYTES>>>(x, Wq, q, NTOK, D_MODEL, D_MODEL);
    sgemm_mma<<<gg, 256, SMEM_BYTES>>>(x, Wk, k, NTOK, D_MODEL, D_MODEL);
    sgemm_mma<<<gg, 256, SMEM_BYTES>>>(x, Wv, v, NTOK, D_MODEL, D_MODEL);

    attn_kernel<<<dim3(SEQ / 64, NH, BATCH), 256>>>(q, k, v, ctx);

    sgemm_mma<<<gg, 256, SMEM_BYTES>>>(ctx, Wo, out, NTOK, D_MODEL, D_MODEL);
}

// round 4
// speedup vs baseline: 2.6330x; 1.6136x over previous
#include <cuda_runtime.h>
#include <math.h>
#include <stdint.h>

#define D_MODEL 1024
#define NH      16
#define DH      64
#define BATCH   2
#define SEQ     2048
#define NTOK    (BATCH * SEQ)   // 4096

// Scratch (device globals — no runtime allocation allowed)
__device__ float g_q[NTOK * D_MODEL];
__device__ float g_k[NTOK * D_MODEL];
__device__ float g_v[NTOK * D_MODEL];
__device__ float g_ctx[NTOK * D_MODEL];

__device__ __forceinline__ uint32_t smem_u32(const void* p) {
    uint32_t a;
    asm("{ .reg .u64 t; cvta.to.shared.u64 t, %1; cvt.u32.u64 %0, t; }" : "=r"(a) : "l"(p));
    return a;
}
__device__ __forceinline__ void ldsm_x4(uint32_t (&r)[4], uint32_t addr) {
    asm volatile("ldmatrix.sync.aligned.m8n8.x4.shared.b16 {%0,%1,%2,%3}, [%4];"
                 : "=r"(r[0]), "=r"(r[1]), "=r"(r[2]), "=r"(r[3]) : "r"(addr));
}
__device__ __forceinline__ void cvt_tf32(uint32_t& x) {
    asm volatile("cvt.rna.tf32.f32 %0, %0;" : "+r"(x));
}
__device__ __forceinline__ void mma_tf32(float (&c)[4], const uint32_t a[4],
                                         uint32_t b0, uint32_t b1) {
    asm volatile(
        "mma.sync.aligned.m16n8k8.row.col.f32.tf32.tf32.f32 "
        "{%0,%1,%2,%3}, {%4,%5,%6,%7}, {%8,%9}, {%0,%1,%2,%3};"
        : "+f"(c[0]), "+f"(c[1]), "+f"(c[2]), "+f"(c[3])
        : "r"(a[0]), "r"(a[1]), "r"(a[2]), "r"(a[3]), "r"(b0), "r"(b1));
}
// Dekker split into tf32 hi/lo
__device__ __forceinline__ void split_tf32(uint32_t x, uint32_t& hi, uint32_t& lo) {
    hi = x; cvt_tf32(hi);
    float lf = __uint_as_float(x) - __uint_as_float(hi);
    lo = __float_as_uint(lf); cvt_tf32(lo);
}
#define CP_ASYNC16(dst, src) \
    asm volatile("cp.async.cg.shared.global [%0], [%1], 16;" :: "r"(dst), "l"(src) : "memory")
#define CP_COMMIT() asm volatile("cp.async.commit_group;" ::: "memory")
#define CP_WAIT0()  asm volatile("cp.async.wait_group 0;" ::: "memory")
#define CP_WAIT1()  asm volatile("cp.async.wait_group 1;" ::: "memory")

// ============================================================================
// TF32 tensor-core GEMM (unchanged from R3): C[M,N] = A[M,K] @ W[N,K]^T
// ============================================================================
#define BM 128
#define BN 128
#define BK 32
#define KSTR 36
#define TILE_F (BM * KSTR)
#define SMEM_FLOATS (4 * TILE_F)
#define SMEM_BYTES (SMEM_FLOATS * 4)

__global__ __launch_bounds__(256) void sgemm_mma(
    const float* __restrict__ A, const float* __restrict__ W,
    float* __restrict__ C, int M, int N, int K)
{
    extern __shared__ float sm[];
    float* AsP[2] = { sm,              sm + TILE_F };
    float* BsP[2] = { sm + 2 * TILE_F, sm + 3 * TILE_F };

    const int tid  = threadIdx.x;
    const int wid  = tid >> 5;
    const int lane = tid & 31;
    const int bm   = blockIdx.y * BM;
    const int bn   = blockIdx.x * BN;
    const int wm = (wid >> 2) * 64;
    const int wn = (wid & 3) * 32;

    float acc[4][4][4];
#pragma unroll
    for (int i = 0; i < 4; i++)
#pragma unroll
        for (int j = 0; j < 4; j++)
#pragma unroll
            for (int q = 0; q < 4; q++) acc[i][j][q] = 0.f;

    const int aj = lane >> 3;
    const int arow = ((aj & 1) << 3) + (lane & 7);
    const int acol = (aj >> 1) << 2;
    const int brow = ((aj >> 1) << 3) + (lane & 7);
    const int bcol = (aj & 1) << 2;

    uint32_t aAddr[2][4], bAddr[2][2];
#pragma unroll
    for (int buf = 0; buf < 2; buf++) {
#pragma unroll
        for (int mt = 0; mt < 4; mt++)
            aAddr[buf][mt] = smem_u32(AsP[buf] + (wm + mt * 16 + arow) * KSTR + acol);
#pragma unroll
        for (int p = 0; p < 2; p++)
            bAddr[buf][p] = smem_u32(BsP[buf] + (wn + p * 16 + brow) * KSTR + bcol);
    }

    const float* Ap = A + (size_t)bm * K;
    const float* Wp = W + (size_t)bn * K;
    const int KT = K / BK;

    auto load_tile = [&](int t, int buf) {
        const float* Ag = Ap + t * BK;
        const float* Bg = Wp + t * BK;
        uint32_t sa = smem_u32(AsP[buf]);
        uint32_t sb = smem_u32(BsP[buf]);
#pragma unroll
        for (int i = 0; i < 4; i++) {
            int chunk = tid + 256 * i;
            int row = chunk >> 3;
            int c   = chunk & 7;
            uint32_t so = (uint32_t)(row * KSTR + c * 4) * 4u;
            CP_ASYNC16(sa + so, __cvta_generic_to_global(Ag + (size_t)row * K + c * 4));
            CP_ASYNC16(sb + so, __cvta_generic_to_global(Bg + (size_t)row * K + c * 4));
        }
        CP_COMMIT();
    };

    load_tile(0, 0);

    for (int t = 0; t < KT; t++) {
        const int buf = t & 1;
        if (t + 1 < KT) { load_tile(t + 1, buf ^ 1); CP_WAIT1(); }
        else           { CP_WAIT0(); }
        __syncthreads();

#pragma unroll
        for (int ks = 0; ks < 4; ks++) {
            uint32_t afr[4][4], bfr[2][4];
#pragma unroll
            for (int mt = 0; mt < 4; mt++) ldsm_x4(afr[mt], aAddr[buf][mt] + ks * 32);
#pragma unroll
            for (int p = 0; p < 2; p++)    ldsm_x4(bfr[p],  bAddr[buf][p]  + ks * 32);
#pragma unroll
            for (int mt = 0; mt < 4; mt++)
#pragma unroll
                for (int q = 0; q < 4; q++) cvt_tf32(afr[mt][q]);
#pragma unroll
            for (int p = 0; p < 2; p++)
#pragma unroll
                for (int q = 0; q < 4; q++) cvt_tf32(bfr[p][q]);
#pragma unroll
            for (int mt = 0; mt < 4; mt++)
#pragma unroll
                for (int nt = 0; nt < 4; nt++)
                    mma_tf32(acc[mt][nt], afr[mt], bfr[nt >> 1][(nt & 1) * 2],
                             bfr[nt >> 1][(nt & 1) * 2 + 1]);
        }
        __syncthreads();
    }

    const int rr = lane >> 2;
    const int cc = (lane & 3) * 2;
#pragma unroll
    for (int mt = 0; mt < 4; mt++) {
#pragma unroll
        for (int nt = 0; nt < 4; nt++) {
            int row = bm + wm + mt * 16 + rr;
            int col = bn + wn + nt * 8 + cc;
            *reinterpret_cast<float2*>(C + (size_t)row * N + col)
                = make_float2(acc[mt][nt][0], acc[mt][nt][1]);
            *reinterpret_cast<float2*>(C + (size_t)(row + 8) * N + col)
                = make_float2(acc[mt][nt][2], acc[mt][nt][3]);
        }
    }
}

// ============================================================================
// Tensor-core causal flash attention (tf32 mma.sync, split-K/V for precision)
// BQ=128 q-rows per CTA, 8 warps x 16 rows; k-tiles of 64.
// smem: Qs[128][68] (reused as P after Q-frag preload), K double buf [64][68],
//       Vt double buf [64][68] (V transposed: [d][kpos]).
// ============================================================================
#define AT_STR 68
#define AQS_OFF 0                      // 128*68 = 8704 words
#define AK_OFF(buf) (8704 + (buf) * 4352)
#define AV_OFF(buf) (17408 + (buf) * 4352)
#define AT_SMEM_WORDS 26112
#define AT_SMEM_BYTES (AT_SMEM_WORDS * 4)   // 104448

__global__ __launch_bounds__(256, 1) void attn_mma(
    const float* __restrict__ Q, const float* __restrict__ K,
    const float* __restrict__ V, float* __restrict__ O)
{
    extern __shared__ float sm[];
    const int tid  = threadIdx.x;
    const int wid  = tid >> 5;
    const int lane = tid & 31;
    const int qt   = (SEQ / 128 - 1) - blockIdx.x;   // long blocks first
    const int h    = blockIdx.y;
    const int b    = blockIdx.z;
    const int q0   = qt * 128;
    const int nkt  = 2 * qt + 2;
    const size_t hb = (size_t)b * SEQ * D_MODEL + (size_t)h * DH;

    float* Qs = sm + AQS_OFF;

    // ---- Q tile load (cp.async), then K0 + V0 prefetch overlapped ----
    {
        uint32_t qdst = smem_u32(Qs);
#pragma unroll
        for (int i = 0; i < 8; i++) {
            int chunk = tid + 256 * i;           // 0..2047
            int row = chunk >> 4, c = chunk & 15;
            CP_ASYNC16(qdst + (uint32_t)(row * AT_STR + c * 4) * 4u,
                       __cvta_generic_to_global(Q + hb + (size_t)(q0 + row) * D_MODEL + c * 4));
        }
        CP_COMMIT();
    }
    // K tile 0
    {
        uint32_t kdst = smem_u32(sm + AK_OFF(0));
#pragma unroll
        for (int i = 0; i < 4; i++) {
            int chunk = tid + 256 * i;           // 0..1023
            int row = chunk >> 4, c = chunk & 15;
            CP_ASYNC16(kdst + (uint32_t)(row * AT_STR + c * 4) * 4u,
                       __cvta_generic_to_global(K + hb + (size_t)row * D_MODEL + c * 4));
        }
        CP_COMMIT();
    }
    // V tile 0 into registers (transposed store later)
    float vpre[16];
    {
        const float* Vb = V + hb;
#pragma unroll
        for (int it = 0; it < 16; it++) {
            int idx = tid + 256 * it;            // 0..4095
            int d = idx & 63, kp = idx >> 6;
            vpre[it] = __ldg(Vb + (size_t)kp * D_MODEL + d);
        }
    }

    // fragment lane mapping
    const int aj   = lane >> 3;
    const int arow = ((aj & 1) << 3) + (lane & 7);
    const int acol = (aj >> 1) << 2;
    const int brow = ((aj >> 1) << 3) + (lane & 7);
    const int bcol = (aj & 1) << 2;
    const int wq   = wid * 16;

    CP_WAIT1();            // Q group done (K0 may still be in flight)
    __syncthreads();

    // Preload Q fragments (scaled by 1/sqrt(64)=0.125, rounded to tf32)
    uint32_t qfr[8][4];
    {
        uint32_t qa = smem_u32(Qs + (wq + arow) * AT_STR + acol);
#pragma unroll
        for (int ks = 0; ks < 8; ks++) {
            ldsm_x4(qfr[ks], qa + ks * 32);
#pragma unroll
            for (int r = 0; r < 4; r++) {
                float f = __uint_as_float(qfr[ks][r]) * 0.125f;
                uint32_t u = __float_as_uint(f);
                cvt_tf32(u);
                qfr[ks][r] = u;
            }
        }
    }
    // NOTE: Qs region is reused as P below. Safe: every thread passes the
    // loop-top __syncthreads() (kt=0) after extracting its Q fragments.

    float* Ps = Qs;
    const uint32_t pLd = smem_u32(Ps + (wq + arow) * AT_STR + acol);
    uint32_t kBase[2] = { smem_u32(sm + AK_OFF(0) + brow * AT_STR + bcol),
                          smem_u32(sm + AK_OFF(1) + brow * AT_STR + bcol) };
    uint32_t vBase[2] = { smem_u32(sm + AV_OFF(0) + brow * AT_STR + bcol),
                          smem_u32(sm + AV_OFF(1) + brow * AT_STR + bcol) };

    float oacc[8][4];
#pragma unroll
    for (int nt = 0; nt < 8; nt++)
#pragma unroll
        for (int r = 0; r < 4; r++) oacc[nt][r] = 0.f;
    float m0 = -INFINITY, m1 = -INFINITY, l0 = 0.f, l1 = 0.f;

    const int lr = lane >> 2;          // fragment row within 8
    const int lc = (lane & 3) * 2;     // fragment col pair base

    for (int kt = 0; kt < nkt; kt++) {
        const int buf = kt & 1;
        const int k0  = kt * 64;
        CP_WAIT0();
        __syncthreads();

        // store prefetched V (transposed) into Vt[buf]
        {
            float* Vt = sm + AV_OFF(buf);
#pragma unroll
            for (int it = 0; it < 16; it++) {
                int idx = tid + 256 * it;
                int d = idx & 63, kp = idx >> 6;
                Vt[d * AT_STR + kp] = vpre[it];
            }
        }
        // prefetch next K (cp.async) and V (regs)
        if (kt + 1 < nkt) {
            uint32_t kdst = smem_u32(sm + AK_OFF(buf ^ 1));
            const float* Kg = K + hb + (size_t)(k0 + 64) * D_MODEL;
#pragma unroll
            for (int i = 0; i < 4; i++) {
                int chunk = tid + 256 * i;
                int row = chunk >> 4, c = chunk & 15;
                CP_ASYNC16(kdst + (uint32_t)(row * AT_STR + c * 4) * 4u,
                           __cvta_generic_to_global(Kg + (size_t)row * D_MODEL + c * 4));
            }
            CP_COMMIT();
            const float* Vg = V + hb + (size_t)(k0 + 64) * D_MODEL;
#pragma unroll
            for (int it = 0; it < 16; it++) {
                int idx = tid + 256 * it;
                int d = idx & 63, kp = idx >> 6;
                vpre[it] = __ldg(Vg + (size_t)kp * D_MODEL + d);
            }
        }
        __syncthreads();

        // ---- S = Q K^T (split-K: 2 mmas per pair) ----
        float sacc[8][4];
#pragma unroll
        for (int nt = 0; nt < 8; nt++)
#pragma unroll
            for (int r = 0; r < 4; r++) sacc[nt][r] = 0.f;

#pragma unroll
        for (int ks = 0; ks < 8; ks++) {
#pragma unroll
            for (int p = 0; p < 4; p++) {
                uint32_t kf[4], khi[4], klo[4];
                ldsm_x4(kf, kBase[buf] + (uint32_t)(p * 16 * AT_STR * 4) + ks * 32);
#pragma unroll
                for (int r = 0; r < 4; r++) split_tf32(kf[r], khi[r], klo[r]);
                mma_tf32(sacc[2 * p],     qfr[ks], khi[0], khi[1]);
                mma_tf32(sacc[2 * p],     qfr[ks], klo[0], klo[1]);
                mma_tf32(sacc[2 * p + 1], qfr[ks], khi[2], khi[3]);
                mma_tf32(sacc[2 * p + 1], qfr[ks], klo[2], klo[3]);
            }
        }

        const int rg0 = q0 + wq + lr;
        // ---- causal mask (only tiles with k0 >= q0 can cross the diagonal) ----
        if (kt >= 2 * qt) {
#pragma unroll
            for (int nt = 0; nt < 8; nt++) {
                int cb = k0 + nt * 8 + lc;
                if (cb     > rg0)     sacc[nt][0] = -1e30f;
                if (cb + 1 > rg0)     sacc[nt][1] = -1e30f;
                if (cb     > rg0 + 8) sacc[nt][2] = -1e30f;
                if (cb + 1 > rg0 + 8) sacc[nt][3] = -1e30f;
            }
        }

        // ---- online softmax ----
        float mx0 = -1e30f, mx1 = -1e30f;
#pragma unroll
        for (int nt = 0; nt < 8; nt++) {
            mx0 = fmaxf(mx0, fmaxf(sacc[nt][0], sacc[nt][1]));
            mx1 = fmaxf(mx1, fmaxf(sacc[nt][2], sacc[nt][3]));
        }
        mx0 = fmaxf(mx0, __shfl_xor_sync(0xffffffffu, mx0, 1));
        mx0 = fmaxf(mx0, __shfl_xor_sync(0xffffffffu, mx0, 2));
        mx1 = fmaxf(mx1, __shfl_xor_sync(0xffffffffu, mx1, 1));
        mx1 = fmaxf(mx1, __shfl_xor_sync(0xffffffffu, mx1, 2));
        float mn0 = fmaxf(m0, mx0), mn1 = fmaxf(m1, mx1);
        float a0 = __expf(m0 - mn0), a1 = __expf(m1 - mn1);
        float rs0 = 0.f, rs1 = 0.f;
#pragma unroll
        for (int nt = 0; nt < 8; nt++) {
            float e0 = __expf(sacc[nt][0] - mn0);
            float e1 = __expf(sacc[nt][1] - mn0);
            float e2 = __expf(sacc[nt][2] - mn1);
            float e3 = __expf(sacc[nt][3] - mn1);
            sacc[nt][0] = e0; sacc[nt][1] = e1; sacc[nt][2] = e2; sacc[nt][3] = e3;
            rs0 += e0 + e1; rs1 += e2 + e3;
        }
        rs0 += __shfl_xor_sync(0xffffffffu, rs0, 1);
        rs0 += __shfl_xor_sync(0xffffffffu, rs0, 2);
        rs1 += __shfl_xor_sync(0xffffffffu, rs1, 1);
        rs1 += __shfl_xor_sync(0xffffffffu, rs1, 2);
        l0 = l0 * a0 + rs0; m0 = mn0;
        l1 = l1 * a1 + rs1; m1 = mn1;
#pragma unroll
        for (int nt = 0; nt < 8; nt++) {
            oacc[nt][0] *= a0; oacc[nt][1] *= a0;
            oacc[nt][2] *= a1; oacc[nt][3] *= a1;
        }

        // ---- stash P into smem (warp-local region) ----
        {
            float* pr0 = Ps + (wq + lr) * AT_STR + lc;
            float* pr1 = pr0 + 8 * AT_STR;
#pragma unroll
            for (int nt = 0; nt < 8; nt++) {
                *reinterpret_cast<float2*>(pr0 + nt * 8) = make_float2(sacc[nt][0], sacc[nt][1]);
                *reinterpret_cast<float2*>(pr1 + nt * 8) = make_float2(sacc[nt][2], sacc[nt][3]);
            }
        }
        __syncwarp();

        // ---- O += P V (split-V: 2 mmas per pair) ----
#pragma unroll
        for (int ks = 0; ks < 8; ks++) {
            uint32_t pf[4];
            ldsm_x4(pf, pLd + ks * 32);
#pragma unroll
            for (int r = 0; r < 4; r++) cvt_tf32(pf[r]);
#pragma unroll
            for (int p = 0; p < 4; p++) {
                uint32_t vf[4], vhi[4], vlo[4];
                ldsm_x4(vf, vBase[buf] + (uint32_t)(p * 16 * AT_STR * 4) + ks * 32);
#pragma unroll
                for (int r = 0; r < 4; r++) split_tf32(vf[r], vhi[r], vlo[r]);
                mma_tf32(oacc[2 * p],     pf, vhi[0], vhi[1]);
                mma_tf32(oacc[2 * p],     pf, vlo[0], vlo[1]);
                mma_tf32(oacc[2 * p + 1], pf, vhi[2], vhi[3]);
                mma_tf32(oacc[2 * p + 1], pf, vlo[2], vlo[3]);
            }
        }
    }

    // ---- epilogue ----
    const float i0 = 1.f / l0, i1 = 1.f / l1;
    const int row0 = q0 + wq + lr;
    float* Ob = O + (size_t)(b * SEQ + row0) * D_MODEL + (size_t)h * DH + lc;
#pragma unroll
    for (int nt = 0; nt < 8; nt++) {
        *reinterpret_cast<float2*>(Ob + nt * 8)
            = make_float2(oacc[nt][0] * i0, oacc[nt][1] * i0);
        *reinterpret_cast<float2*>(Ob + 8 * D_MODEL + nt * 8)
            = make_float2(oacc[nt][2] * i1, oacc[nt][3] * i1);
    }
}

// ---------------------------------------------------------------------------
extern "C" void kernel_launch(void* const* d_in, const int* in_sizes, int n_in,
                              void* d_out, int out_size)
{
    const float* x  = (const float*)d_in[0];
    const float* Wq = (const float*)d_in[1];
    const float* Wk = (const float*)d_in[2];
    const float* Wv = (const float*)d_in[3];
    const float* Wo = (const float*)d_in[4];
    float* out = (float*)d_out;

    float *q, *k, *v, *ctx;
    cudaGetSymbolAddress((void**)&q,   g_q);
    cudaGetSymbolAddress((void**)&k,   g_k);
    cudaGetSymbolAddress((void**)&v,   g_v);
    cudaGetSymbolAddress((void**)&ctx, g_ctx);

    cudaFuncSetAttribute(sgemm_mma, cudaFuncAttributeMaxDynamicSharedMemorySize, SMEM_BYTES);
    cudaFuncSetAttribute(attn_mma,  cudaFuncAttributeMaxDynamicSharedMemorySize, AT_SMEM_BYTES);

    dim3 gg(D_MODEL / BN, NTOK / BM);   // (8, 32)
    sgemm_mma<<<gg, 256, SMEM_BYTES>>>(x, Wq, q, NTOK, D_MODEL, D_MODEL);
    sgemm_mma<<<gg, 256, SMEM_BYTES>>>(x, Wk, k, NTOK, D_MODEL, D_MODEL);
    sgemm_mma<<<gg, 256, SMEM_BYTES>>>(x, Wv, v, NTOK, D_MODEL, D_MODEL);

    attn_mma<<<dim3(SEQ / 128, NH, BATCH), 256, AT_SMEM_BYTES>>>(q, k, v, ctx);

    sgemm_mma<<<gg, 256, SMEM_BYTES>>>(ctx, Wo, out, NTOK, D_MODEL, D_MODEL);
}

// round 5
// speedup vs baseline: 2.8728x; 1.0911x over previous
#include <cuda_runtime.h>
#include <math.h>
#include <stdint.h>

#define D_MODEL 1024
#define NH      16
#define DH      64
#define BATCH   2
#define SEQ     2048
#define NTOK    (BATCH * SEQ)   // 4096

// Scratch (device globals — no runtime allocation allowed)
__device__ float g_q[NTOK * D_MODEL];
__device__ float g_k[NTOK * D_MODEL];
__device__ float g_v[NTOK * D_MODEL];
__device__ float g_ctx[NTOK * D_MODEL];

__device__ __forceinline__ uint32_t smem_u32(const void* p) {
    uint32_t a;
    asm("{ .reg .u64 t; cvta.to.shared.u64 t, %1; cvt.u32.u64 %0, t; }" : "=r"(a) : "l"(p));
    return a;
}
__device__ __forceinline__ void ldsm_x4(uint32_t (&r)[4], uint32_t addr) {
    asm volatile("ldmatrix.sync.aligned.m8n8.x4.shared.b16 {%0,%1,%2,%3}, [%4];"
                 : "=r"(r[0]), "=r"(r[1]), "=r"(r[2]), "=r"(r[3]) : "r"(addr));
}
__device__ __forceinline__ void cvt_tf32(uint32_t& x) {
    asm volatile("cvt.rna.tf32.f32 %0, %0;" : "+r"(x));
}
__device__ __forceinline__ void mma_tf32(float (&c)[4], const uint32_t a[4],
                                         uint32_t b0, uint32_t b1) {
    asm volatile(
        "mma.sync.aligned.m16n8k8.row.col.f32.tf32.tf32.f32 "
        "{%0,%1,%2,%3}, {%4,%5,%6,%7}, {%8,%9}, {%0,%1,%2,%3};"
        : "+f"(c[0]), "+f"(c[1]), "+f"(c[2]), "+f"(c[3])
        : "r"(a[0]), "r"(a[1]), "r"(a[2]), "r"(a[3]), "r"(b0), "r"(b1));
}
// Dekker split into tf32 hi/lo (float form, producer-side)
__device__ __forceinline__ void splitf(float x, float& hi, float& lo) {
    uint32_t u = __float_as_uint(x); cvt_tf32(u);
    hi = __uint_as_float(u);
    float l = x - hi;
    uint32_t ul = __float_as_uint(l); cvt_tf32(ul);
    lo = __uint_as_float(ul);
}
__device__ __forceinline__ float ex2(float x) {
    float y; asm("ex2.approx.f32 %0, %1;" : "=f"(y) : "f"(x)); return y;
}
#define CP_ASYNC16(dst, src) \
    asm volatile("cp.async.cg.shared.global [%0], [%1], 16;" :: "r"(dst), "l"(src) : "memory")
#define CP_COMMIT() asm volatile("cp.async.commit_group;" ::: "memory")
#define CP_WAIT0()  asm volatile("cp.async.wait_group 0;" ::: "memory")
#define CP_WAIT1()  asm volatile("cp.async.wait_group 1;" ::: "memory")

// ============================================================================
// TF32 tensor-core GEMM (unchanged from R3): C[M,N] = A[M,K] @ W[N,K]^T
// ============================================================================
#define BM 128
#define BN 128
#define BK 32
#define KSTR 36
#define TILE_F (BM * KSTR)
#define SMEM_FLOATS (4 * TILE_F)
#define SMEM_BYTES (SMEM_FLOATS * 4)

__global__ __launch_bounds__(256) void sgemm_mma(
    const float* __restrict__ A, const float* __restrict__ W,
    float* __restrict__ C, int M, int N, int K)
{
    extern __shared__ float sm[];
    float* AsP[2] = { sm,              sm + TILE_F };
    float* BsP[2] = { sm + 2 * TILE_F, sm + 3 * TILE_F };

    const int tid  = threadIdx.x;
    const int wid  = tid >> 5;
    const int lane = tid & 31;
    const int bm   = blockIdx.y * BM;
    const int bn   = blockIdx.x * BN;
    const int wm = (wid >> 2) * 64;
    const int wn = (wid & 3) * 32;

    float acc[4][4][4];
#pragma unroll
    for (int i = 0; i < 4; i++)
#pragma unroll
        for (int j = 0; j < 4; j++)
#pragma unroll
            for (int q = 0; q < 4; q++) acc[i][j][q] = 0.f;

    const int aj = lane >> 3;
    const int arow = ((aj & 1) << 3) + (lane & 7);
    const int acol = (aj >> 1) << 2;
    const int brow = ((aj >> 1) << 3) + (lane & 7);
    const int bcol = (aj & 1) << 2;

    uint32_t aAddr[2][4], bAddr[2][2];
#pragma unroll
    for (int buf = 0; buf < 2; buf++) {
#pragma unroll
        for (int mt = 0; mt < 4; mt++)
            aAddr[buf][mt] = smem_u32(AsP[buf] + (wm + mt * 16 + arow) * KSTR + acol);
#pragma unroll
        for (int p = 0; p < 2; p++)
            bAddr[buf][p] = smem_u32(BsP[buf] + (wn + p * 16 + brow) * KSTR + bcol);
    }

    const float* Ap = A + (size_t)bm * K;
    const float* Wp = W + (size_t)bn * K;
    const int KT = K / BK;

    auto load_tile = [&](int t, int buf) {
        const float* Ag = Ap + t * BK;
        const float* Bg = Wp + t * BK;
        uint32_t sa = smem_u32(AsP[buf]);
        uint32_t sb = smem_u32(BsP[buf]);
#pragma unroll
        for (int i = 0; i < 4; i++) {
            int chunk = tid + 256 * i;
            int row = chunk >> 3;
            int c   = chunk & 7;
            uint32_t so = (uint32_t)(row * KSTR + c * 4) * 4u;
            CP_ASYNC16(sa + so, __cvta_generic_to_global(Ag + (size_t)row * K + c * 4));
            CP_ASYNC16(sb + so, __cvta_generic_to_global(Bg + (size_t)row * K + c * 4));
        }
        CP_COMMIT();
    };

    load_tile(0, 0);

    for (int t = 0; t < KT; t++) {
        const int buf = t & 1;
        if (t + 1 < KT) { load_tile(t + 1, buf ^ 1); CP_WAIT1(); }
        else           { CP_WAIT0(); }
        __syncthreads();

#pragma unroll
        for (int ks = 0; ks < 4; ks++) {
            uint32_t afr[4][4], bfr[2][4];
#pragma unroll
            for (int mt = 0; mt < 4; mt++) ldsm_x4(afr[mt], aAddr[buf][mt] + ks * 32);
#pragma unroll
            for (int p = 0; p < 2; p++)    ldsm_x4(bfr[p],  bAddr[buf][p]  + ks * 32);
#pragma unroll
            for (int mt = 0; mt < 4; mt++)
#pragma unroll
                for (int q = 0; q < 4; q++) cvt_tf32(afr[mt][q]);
#pragma unroll
            for (int p = 0; p < 2; p++)
#pragma unroll
                for (int q = 0; q < 4; q++) cvt_tf32(bfr[p][q]);
#pragma unroll
            for (int mt = 0; mt < 4; mt++)
#pragma unroll
                for (int nt = 0; nt < 4; nt++)
                    mma_tf32(acc[mt][nt], afr[mt], bfr[nt >> 1][(nt & 1) * 2],
                             bfr[nt >> 1][(nt & 1) * 2 + 1]);
        }
        __syncthreads();
    }

    const int rr = lane >> 2;
    const int cc = (lane & 3) * 2;
#pragma unroll
    for (int mt = 0; mt < 4; mt++) {
#pragma unroll
        for (int nt = 0; nt < 4; nt++) {
            int row = bm + wm + mt * 16 + rr;
            int col = bn + wn + nt * 8 + cc;
            *reinterpret_cast<float2*>(C + (size_t)row * N + col)
                = make_float2(acc[mt][nt][0], acc[mt][nt][1]);
            *reinterpret_cast<float2*>(C + (size_t)(row + 8) * N + col)
                = make_float2(acc[mt][nt][2], acc[mt][nt][3]);
        }
    }
}

// ============================================================================
// Tensor-core causal flash attention, tf32 mma.sync.
// R5: pre-split K/V into hi/lo smem tiles ONCE per CTA per ktile (producer
// stage) instead of per-warp in the mma loop; ex2-domain softmax.
// smem (words): Q/P 8704 | Kraw x2 8704 | KH 4352 | KL 4352 | VH 4352 | VL 4352
// ============================================================================
#define AT_STR 68
#define AQS_OFF   0
#define AKRAW_OFF(b) (8704 + (b) * 4352)
#define AKH_OFF   17408
#define AKL_OFF   21760
#define AVH_OFF   26112
#define AVL_OFF   30464
#define AT_SMEM_WORDS 34816
#define AT_SMEM_BYTES (AT_SMEM_WORDS * 4)   // 139264

__global__ __launch_bounds__(256, 1) void attn_mma(
    const float* __restrict__ Q, const float* __restrict__ K,
    const float* __restrict__ V, float* __restrict__ O)
{
    extern __shared__ float sm[];
    const int tid  = threadIdx.x;
    const int wid  = tid >> 5;
    const int lane = tid & 31;
    const int qt   = (SEQ / 128 - 1) - blockIdx.x;   // long blocks first
    const int h    = blockIdx.y;
    const int b    = blockIdx.z;
    const int q0   = qt * 128;
    const int nkt  = 2 * qt + 2;
    const size_t hb = (size_t)b * SEQ * D_MODEL + (size_t)h * DH;

    float* Qs = sm + AQS_OFF;

    // ---- Q tile load (cp.async, group A) ----
    {
        uint32_t qdst = smem_u32(Qs);
#pragma unroll
        for (int i = 0; i < 8; i++) {
            int chunk = tid + 256 * i;           // 0..2047
            int row = chunk >> 4, c = chunk & 15;
            CP_ASYNC16(qdst + (uint32_t)(row * AT_STR + c * 4) * 4u,
                       __cvta_generic_to_global(Q + hb + (size_t)(q0 + row) * D_MODEL + c * 4));
        }
        CP_COMMIT();
    }
    // ---- K raw tile 0 (cp.async, group B) ----
    {
        uint32_t kdst = smem_u32(sm + AKRAW_OFF(0));
#pragma unroll
        for (int i = 0; i < 4; i++) {
            int chunk = tid + 256 * i;           // 0..1023
            int row = chunk >> 4, c = chunk & 15;
            CP_ASYNC16(kdst + (uint32_t)(row * AT_STR + c * 4) * 4u,
                       __cvta_generic_to_global(K + hb + (size_t)row * D_MODEL + c * 4));
        }
        CP_COMMIT();
    }
    // ---- V tile 0 into registers ----
    float vpre[16];
    {
        const float* Vb = V + hb;
#pragma unroll
        for (int it = 0; it < 16; it++) {
            int idx = tid + 256 * it;            // 0..4095
            int d = idx & 63, kp = idx >> 6;
            vpre[it] = __ldg(Vb + (size_t)kp * D_MODEL + d);
        }
    }

    // fragment lane mapping
    const int aj   = lane >> 3;
    const int arow = ((aj & 1) << 3) + (lane & 7);
    const int acol = (aj >> 1) << 2;
    const int brow = ((aj >> 1) << 3) + (lane & 7);
    const int bcol = (aj & 1) << 2;
    const int wq   = wid * 16;

    CP_WAIT1();            // Q group done (K0 may still be in flight)
    __syncthreads();

    // Preload Q fragments, scaled by (1/8)*log2(e), rounded to tf32
    const float QSCALE = 0.125f * 1.4426950408889634f;
    uint32_t qfr[8][4];
    {
        uint32_t qa = smem_u32(Qs + (wq + arow) * AT_STR + acol);
#pragma unroll
        for (int ks = 0; ks < 8; ks++) {
            ldsm_x4(qfr[ks], qa + ks * 32);
#pragma unroll
            for (int r = 0; r < 4; r++) {
                float f = __uint_as_float(qfr[ks][r]) * QSCALE;
                uint32_t u = __float_as_uint(f);
                cvt_tf32(u);
                qfr[ks][r] = u;
            }
        }
    }
    // Qs region is reused as P below (safe: all threads hold Q in regs and
    // pass the loop-top __syncthreads before any P store).

    float* Ps = Qs;
    const uint32_t pLd   = smem_u32(Ps + (wq + arow) * AT_STR + acol);
    const uint32_t kHiB  = smem_u32(sm + AKH_OFF + brow * AT_STR + bcol);
    const uint32_t kLoB  = smem_u32(sm + AKL_OFF + brow * AT_STR + bcol);
    const uint32_t vHiB  = smem_u32(sm + AVH_OFF + brow * AT_STR + bcol);
    const uint32_t vLoB  = smem_u32(sm + AVL_OFF + brow * AT_STR + bcol);

    float oacc[8][4];
#pragma unroll
    for (int nt = 0; nt < 8; nt++)
#pragma unroll
        for (int r = 0; r < 4; r++) oacc[nt][r] = 0.f;
    float m0 = -INFINITY, m1 = -INFINITY, l0 = 0.f, l1 = 0.f;

    const int lr = lane >> 2;
    const int lc = (lane & 3) * 2;

    for (int kt = 0; kt < nkt; kt++) {
        const int buf = kt & 1;
        const int k0  = kt * 64;
        CP_WAIT0();            // Kraw[buf] resident
        __syncthreads();       // all warps done reading KH/KL/VH/VL of kt-1

        // ---- producer: split Kraw -> KH/KL, vpre -> VH/VL (once per CTA) ----
        {
            const float* KR = sm + AKRAW_OFF(buf);
            float* KH = sm + AKH_OFF;
            float* KL = sm + AKL_OFF;
#pragma unroll
            for (int i = 0; i < 4; i++) {
                int chunk = tid + 256 * i;
                int row = chunk >> 4, c = chunk & 15;
                int off = row * AT_STR + c * 4;
                float4 r = *reinterpret_cast<const float4*>(KR + off);
                float4 hi4, lo4;
                splitf(r.x, hi4.x, lo4.x);
                splitf(r.y, hi4.y, lo4.y);
                splitf(r.z, hi4.z, lo4.z);
                splitf(r.w, hi4.w, lo4.w);
                *reinterpret_cast<float4*>(KH + off) = hi4;
                *reinterpret_cast<float4*>(KL + off) = lo4;
            }
            float* VH = sm + AVH_OFF;
            float* VL = sm + AVL_OFF;
#pragma unroll
            for (int it = 0; it < 16; it++) {
                int idx = tid + 256 * it;
                int d = idx & 63, kp = idx >> 6;
                float hv, lv;
                splitf(vpre[it], hv, lv);
                VH[d * AT_STR + kp] = hv;
                VL[d * AT_STR + kp] = lv;
            }
        }
        // ---- prefetch next K (cp.async) and V (regs) ----
        if (kt + 1 < nkt) {
            uint32_t kdst = smem_u32(sm + AKRAW_OFF(buf ^ 1));
            const float* Kg = K + hb + (size_t)(k0 + 64) * D_MODEL;
#pragma unroll
            for (int i = 0; i < 4; i++) {
                int chunk = tid + 256 * i;
                int row = chunk >> 4, c = chunk & 15;
                CP_ASYNC16(kdst + (uint32_t)(row * AT_STR + c * 4) * 4u,
                           __cvta_generic_to_global(Kg + (size_t)row * D_MODEL + c * 4));
            }
            CP_COMMIT();
            const float* Vg = V + hb + (size_t)(k0 + 64) * D_MODEL;
#pragma unroll
            for (int it = 0; it < 16; it++) {
                int idx = tid + 256 * it;
                int d = idx & 63, kp = idx >> 6;
                vpre[it] = __ldg(Vg + (size_t)kp * D_MODEL + d);
            }
        }
        __syncthreads();       // split tiles visible to all warps

        // ---- S = Q K^T ----
        float sacc[8][4];
#pragma unroll
        for (int nt = 0; nt < 8; nt++)
#pragma unroll
            for (int r = 0; r < 4; r++) sacc[nt][r] = 0.f;

#pragma unroll
        for (int ks = 0; ks < 8; ks++) {
#pragma unroll
            for (int p = 0; p < 4; p++) {
                uint32_t khi[4], klo[4];
                uint32_t boff = (uint32_t)(p * 16 * AT_STR * 4) + ks * 32;
                ldsm_x4(khi, kHiB + boff);
                ldsm_x4(klo, kLoB + boff);
                mma_tf32(sacc[2 * p],     qfr[ks], khi[0], khi[1]);
                mma_tf32(sacc[2 * p],     qfr[ks], klo[0], klo[1]);
                mma_tf32(sacc[2 * p + 1], qfr[ks], khi[2], khi[3]);
                mma_tf32(sacc[2 * p + 1], qfr[ks], klo[2], klo[3]);
            }
        }

        const int rg0 = q0 + wq + lr;
        if (kt >= 2 * qt) {      // only diagonal-crossing tiles
#pragma unroll
            for (int nt = 0; nt < 8; nt++) {
                int cb = k0 + nt * 8 + lc;
                if (cb     > rg0)     sacc[nt][0] = -1e30f;
                if (cb + 1 > rg0)     sacc[nt][1] = -1e30f;
                if (cb     > rg0 + 8) sacc[nt][2] = -1e30f;
                if (cb + 1 > rg0 + 8) sacc[nt][3] = -1e30f;
            }
        }

        // ---- online softmax (log2 domain) ----
        float mx0 = -1e30f, mx1 = -1e30f;
#pragma unroll
        for (int nt = 0; nt < 8; nt++) {
            mx0 = fmaxf(mx0, fmaxf(sacc[nt][0], sacc[nt][1]));
            mx1 = fmaxf(mx1, fmaxf(sacc[nt][2], sacc[nt][3]));
        }
        mx0 = fmaxf(mx0, __shfl_xor_sync(0xffffffffu, mx0, 1));
        mx0 = fmaxf(mx0, __shfl_xor_sync(0xffffffffu, mx0, 2));
        mx1 = fmaxf(mx1, __shfl_xor_sync(0xffffffffu, mx1, 1));
        mx1 = fmaxf(mx1, __shfl_xor_sync(0xffffffffu, mx1, 2));
        float mn0 = fmaxf(m0, mx0), mn1 = fmaxf(m1, mx1);
        float a0 = ex2(m0 - mn0), a1 = ex2(m1 - mn1);
        float rs0 = 0.f, rs1 = 0.f;
#pragma unroll
        for (int nt = 0; nt < 8; nt++) {
            float e0 = ex2(sacc[nt][0] - mn0);
            float e1 = ex2(sacc[nt][1] - mn0);
            float e2 = ex2(sacc[nt][2] - mn1);
            float e3 = ex2(sacc[nt][3] - mn1);
            sacc[nt][0] = e0; sacc[nt][1] = e1; sacc[nt][2] = e2; sacc[nt][3] = e3;
            rs0 += e0 + e1; rs1 += e2 + e3;
        }
        rs0 += __shfl_xor_sync(0xffffffffu, rs0, 1);
        rs0 += __shfl_xor_sync(0xffffffffu, rs0, 2);
        rs1 += __shfl_xor_sync(0xffffffffu, rs1, 1);
        rs1 += __shfl_xor_sync(0xffffffffu, rs1, 2);
        l0 = l0 * a0 + rs0; m0 = mn0;
        l1 = l1 * a1 + rs1; m1 = mn1;
#pragma unroll
        for (int nt = 0; nt < 8; nt++) {
            oacc[nt][0] *= a0; oacc[nt][1] *= a0;
            oacc[nt][2] *= a1; oacc[nt][3] *= a1;
        }

        // ---- stash P into smem (warp-local region) ----
        {
            float* pr0 = Ps + (wq + lr) * AT_STR + lc;
            float* pr1 = pr0 + 8 * AT_STR;
#pragma unroll
            for (int nt = 0; nt < 8; nt++) {
                *reinterpret_cast<float2*>(pr0 + nt * 8) = make_float2(sacc[nt][0], sacc[nt][1]);
                *reinterpret_cast<float2*>(pr1 + nt * 8) = make_float2(sacc[nt][2], sacc[nt][3]);
            }
        }
        __syncwarp();

        // ---- O += P V ----
#pragma unroll
        for (int ks = 0; ks < 8; ks++) {
            uint32_t pf[4];
            ldsm_x4(pf, pLd + ks * 32);
#pragma unroll
            for (int r = 0; r < 4; r++) cvt_tf32(pf[r]);
#pragma unroll
            for (int p = 0; p < 4; p++) {
                uint32_t vhi[4], vlo[4];
                uint32_t boff = (uint32_t)(p * 16 * AT_STR * 4) + ks * 32;
                ldsm_x4(vhi, vHiB + boff);
                ldsm_x4(vlo, vLoB + boff);
                mma_tf32(oacc[2 * p],     pf, vhi[0], vhi[1]);
                mma_tf32(oacc[2 * p],     pf, vlo[0], vlo[1]);
                mma_tf32(oacc[2 * p + 1], pf, vhi[2], vhi[3]);
                mma_tf32(oacc[2 * p + 1], pf, vlo[2], vlo[3]);
            }
        }
    }

    // ---- epilogue ----
    const float i0 = 1.f / l0, i1 = 1.f / l1;
    const int row0 = q0 + wq + lr;
    float* Ob = O + (size_t)(b * SEQ + row0) * D_MODEL + (size_t)h * DH + lc;
#pragma unroll
    for (int nt = 0; nt < 8; nt++) {
        *reinterpret_cast<float2*>(Ob + nt * 8)
            = make_float2(oacc[nt][0] * i0, oacc[nt][1] * i0);
        *reinterpret_cast<float2*>(Ob + 8 * D_MODEL + nt * 8)
            = make_float2(oacc[nt][2] * i1, oacc[nt][3] * i1);
    }
}

// ---------------------------------------------------------------------------
extern "C" void kernel_launch(void* const* d_in, const int* in_sizes, int n_in,
                              void* d_out, int out_size)
{
    const float* x  = (const float*)d_in[0];
    const float* Wq = (const float*)d_in[1];
    const float* Wk = (const float*)d_in[2];
    const float* Wv = (const float*)d_in[3];
    const float* Wo = (const float*)d_in[4];
    float* out = (float*)d_out;

    float *q, *k, *v, *ctx;
    cudaGetSymbolAddress((void**)&q,   g_q);
    cudaGetSymbolAddress((void**)&k,   g_k);
    cudaGetSymbolAddress((void**)&v,   g_v);
    cudaGetSymbolAddress((void**)&ctx, g_ctx);

    cudaFuncSetAttribute(sgemm_mma, cudaFuncAttributeMaxDynamicSharedMemorySize, SMEM_BYTES);
    cudaFuncSetAttribute(attn_mma,  cudaFuncAttributeMaxDynamicSharedMemorySize, AT_SMEM_BYTES);

    dim3 gg(D_MODEL / BN, NTOK / BM);   // (8, 32)
    sgemm_mma<<<gg, 256, SMEM_BYTES>>>(x, Wq, q, NTOK, D_MODEL, D_MODEL);
    sgemm_mma<<<gg, 256, SMEM_BYTES>>>(x, Wk, k, NTOK, D_MODEL, D_MODEL);
    sgemm_mma<<<gg, 256, SMEM_BYTES>>>(x, Wv, v, NTOK, D_MODEL, D_MODEL);

    attn_mma<<<dim3(SEQ / 128, NH, BATCH), 256, AT_SMEM_BYTES>>>(q, k, v, ctx);

    sgemm_mma<<<gg, 256, SMEM_BYTES>>>(ctx, Wo, out, NTOK, D_MODEL, D_MODEL);
}

// round 6
// speedup vs baseline: 3.1177x; 1.0852x over previous
#include <cuda_runtime.h>
#include <math.h>
#include <stdint.h>

#define D_MODEL 1024
#define NH      16
#define DH      64
#define BATCH   2
#define SEQ     2048
#define NTOK    (BATCH * SEQ)   // 4096

// Scratch (device globals — no runtime allocation allowed)
__device__ float g_q[NTOK * D_MODEL];
__device__ float g_k[NTOK * D_MODEL];
__device__ float g_v[NTOK * D_MODEL];
__device__ float g_ctx[NTOK * D_MODEL];

__device__ __forceinline__ uint32_t smem_u32(const void* p) {
    uint32_t a;
    asm("{ .reg .u64 t; cvta.to.shared.u64 t, %1; cvt.u32.u64 %0, t; }" : "=r"(a) : "l"(p));
    return a;
}
__device__ __forceinline__ void ldsm_x4(uint32_t (&r)[4], uint32_t addr) {
    asm volatile("ldmatrix.sync.aligned.m8n8.x4.shared.b16 {%0,%1,%2,%3}, [%4];"
                 : "=r"(r[0]), "=r"(r[1]), "=r"(r[2]), "=r"(r[3]) : "r"(addr));
}
__device__ __forceinline__ void cvt_tf32(uint32_t& x) {
    asm volatile("cvt.rna.tf32.f32 %0, %0;" : "+r"(x));
}
__device__ __forceinline__ void mma_tf32(float (&c)[4], const uint32_t a[4],
                                         uint32_t b0, uint32_t b1) {
    asm volatile(
        "mma.sync.aligned.m16n8k8.row.col.f32.tf32.tf32.f32 "
        "{%0,%1,%2,%3}, {%4,%5,%6,%7}, {%8,%9}, {%0,%1,%2,%3};"
        : "+f"(c[0]), "+f"(c[1]), "+f"(c[2]), "+f"(c[3])
        : "r"(a[0]), "r"(a[1]), "r"(a[2]), "r"(a[3]), "r"(b0), "r"(b1));
}
// bf16 two-term split packed into one word: [hi_bf16 (31:16) | lo_bf16 (15:0)]
__device__ __forceinline__ uint32_t bsplit_pack(float x) {
    uint32_t r;
    asm("{.reg .b16 h, l, z;\n\t"
        ".reg .f32 hf, lf;\n\t"
        "mov.b16 z, 0;\n\t"
        "cvt.rn.bf16.f32 h, %1;\n\t"
        "mov.b32 hf, {z, h};\n\t"
        "sub.f32 lf, %1, hf;\n\t"
        "cvt.rn.bf16.f32 l, lf;\n\t"
        "mov.b32 %0, {l, h};\n\t}"
        : "=r"(r) : "f"(x));
    return r;
}
__device__ __forceinline__ float ex2(float x) {
    float y; asm("ex2.approx.f32 %0, %1;" : "=f"(y) : "f"(x)); return y;
}
#define CP_ASYNC16(dst, src) \
    asm volatile("cp.async.cg.shared.global [%0], [%1], 16;" :: "r"(dst), "l"(src) : "memory")
#define CP_COMMIT() asm volatile("cp.async.commit_group;" ::: "memory")
#define CP_WAIT0()  asm volatile("cp.async.wait_group 0;" ::: "memory")
#define CP_WAIT1()  asm volatile("cp.async.wait_group 1;" ::: "memory")

// ============================================================================
// TF32 tensor-core GEMM (unchanged): C[M,N] = A[M,K] @ W[N,K]^T
// ============================================================================
#define BM 128
#define BN 128
#define BK 32
#define KSTR 36
#define TILE_F (BM * KSTR)
#define SMEM_FLOATS (4 * TILE_F)
#define SMEM_BYTES (SMEM_FLOATS * 4)

__global__ __launch_bounds__(256) void sgemm_mma(
    const float* __restrict__ A, const float* __restrict__ W,
    float* __restrict__ C, int M, int N, int K)
{
    extern __shared__ float sm[];
    float* AsP[2] = { sm,              sm + TILE_F };
    float* BsP[2] = { sm + 2 * TILE_F, sm + 3 * TILE_F };

    const int tid  = threadIdx.x;
    const int wid  = tid >> 5;
    const int lane = tid & 31;
    const int bm   = blockIdx.y * BM;
    const int bn   = blockIdx.x * BN;
    const int wm = (wid >> 2) * 64;
    const int wn = (wid & 3) * 32;

    float acc[4][4][4];
#pragma unroll
    for (int i = 0; i < 4; i++)
#pragma unroll
        for (int j = 0; j < 4; j++)
#pragma unroll
            for (int q = 0; q < 4; q++) acc[i][j][q] = 0.f;

    const int aj = lane >> 3;
    const int arow = ((aj & 1) << 3) + (lane & 7);
    const int acol = (aj >> 1) << 2;
    const int brow = ((aj >> 1) << 3) + (lane & 7);
    const int bcol = (aj & 1) << 2;

    uint32_t aAddr[2][4], bAddr[2][2];
#pragma unroll
    for (int buf = 0; buf < 2; buf++) {
#pragma unroll
        for (int mt = 0; mt < 4; mt++)
            aAddr[buf][mt] = smem_u32(AsP[buf] + (wm + mt * 16 + arow) * KSTR + acol);
#pragma unroll
        for (int p = 0; p < 2; p++)
            bAddr[buf][p] = smem_u32(BsP[buf] + (wn + p * 16 + brow) * KSTR + bcol);
    }

    const float* Ap = A + (size_t)bm * K;
    const float* Wp = W + (size_t)bn * K;
    const int KT = K / BK;

    auto load_tile = [&](int t, int buf) {
        const float* Ag = Ap + t * BK;
        const float* Bg = Wp + t * BK;
        uint32_t sa = smem_u32(AsP[buf]);
        uint32_t sb = smem_u32(BsP[buf]);
#pragma unroll
        for (int i = 0; i < 4; i++) {
            int chunk = tid + 256 * i;
            int row = chunk >> 3;
            int c   = chunk & 7;
            uint32_t so = (uint32_t)(row * KSTR + c * 4) * 4u;
            CP_ASYNC16(sa + so, __cvta_generic_to_global(Ag + (size_t)row * K + c * 4));
            CP_ASYNC16(sb + so, __cvta_generic_to_global(Bg + (size_t)row * K + c * 4));
        }
        CP_COMMIT();
    };

    load_tile(0, 0);

    for (int t = 0; t < KT; t++) {
        const int buf = t & 1;
        if (t + 1 < KT) { load_tile(t + 1, buf ^ 1); CP_WAIT1(); }
        else           { CP_WAIT0(); }
        __syncthreads();

#pragma unroll
        for (int ks = 0; ks < 4; ks++) {
            uint32_t afr[4][4], bfr[2][4];
#pragma unroll
            for (int mt = 0; mt < 4; mt++) ldsm_x4(afr[mt], aAddr[buf][mt] + ks * 32);
#pragma unroll
            for (int p = 0; p < 2; p++)    ldsm_x4(bfr[p],  bAddr[buf][p]  + ks * 32);
#pragma unroll
            for (int mt = 0; mt < 4; mt++)
#pragma unroll
                for (int q = 0; q < 4; q++) cvt_tf32(afr[mt][q]);
#pragma unroll
            for (int p = 0; p < 2; p++)
#pragma unroll
                for (int q = 0; q < 4; q++) cvt_tf32(bfr[p][q]);
#pragma unroll
            for (int mt = 0; mt < 4; mt++)
#pragma unroll
                for (int nt = 0; nt < 4; nt++)
                    mma_tf32(acc[mt][nt], afr[mt], bfr[nt >> 1][(nt & 1) * 2],
                             bfr[nt >> 1][(nt & 1) * 2 + 1]);
        }
        __syncthreads();
    }

    const int rr = lane >> 2;
    const int cc = (lane & 3) * 2;
#pragma unroll
    for (int mt = 0; mt < 4; mt++) {
#pragma unroll
        for (int nt = 0; nt < 4; nt++) {
            int row = bm + wm + mt * 16 + rr;
            int col = bn + wn + nt * 8 + cc;
            *reinterpret_cast<float2*>(C + (size_t)row * N + col)
                = make_float2(acc[mt][nt][0], acc[mt][nt][1]);
            *reinterpret_cast<float2*>(C + (size_t)(row + 8) * N + col)
                = make_float2(acc[mt][nt][2], acc[mt][nt][3]);
        }
    }
}

// ============================================================================
// Tensor-core causal flash attention, tf32 mma.sync.
// R6: K/V hi+lo packed into ONE 32-bit word (bf16 split) -> half the LDSM
// traffic; unpack with AND/SHL in regs (bf16<<16 is a valid tf32 pattern).
// smem (words): Q/P 8704 | Kraw x2 8704 | KHL 4352 | VHL 4352 = 104448 B
// ============================================================================
#define AT_STR 68
#define AQS_OFF   0
#define AKRAW_OFF(b) (8704 + (b) * 4352)
#define AKHL_OFF  17408
#define AVHL_OFF  21760
#define AT_SMEM_WORDS 26112
#define AT_SMEM_BYTES (AT_SMEM_WORDS * 4)   // 104448

__global__ __launch_bounds__(256, 1) void attn_mma(
    const float* __restrict__ Q, const float* __restrict__ K,
    const float* __restrict__ V, float* __restrict__ O)
{
    extern __shared__ float sm[];
    const int tid  = threadIdx.x;
    const int wid  = tid >> 5;
    const int lane = tid & 31;
    const int qt   = (SEQ / 128 - 1) - blockIdx.x;   // long blocks first
    const int h    = blockIdx.y;
    const int b    = blockIdx.z;
    const int q0   = qt * 128;
    const int nkt  = 2 * qt + 2;
    const size_t hb = (size_t)b * SEQ * D_MODEL + (size_t)h * DH;

    float* Qs = sm + AQS_OFF;

    // ---- Q tile load (cp.async, group A) ----
    {
        uint32_t qdst = smem_u32(Qs);
#pragma unroll
        for (int i = 0; i < 8; i++) {
            int chunk = tid + 256 * i;           // 0..2047
            int row = chunk >> 4, c = chunk & 15;
            CP_ASYNC16(qdst + (uint32_t)(row * AT_STR + c * 4) * 4u,
                       __cvta_generic_to_global(Q + hb + (size_t)(q0 + row) * D_MODEL + c * 4));
        }
        CP_COMMIT();
    }
    // ---- K raw tile 0 (cp.async, group B) ----
    {
        uint32_t kdst = smem_u32(sm + AKRAW_OFF(0));
#pragma unroll
        for (int i = 0; i < 4; i++) {
            int chunk = tid + 256 * i;           // 0..1023
            int row = chunk >> 4, c = chunk & 15;
            CP_ASYNC16(kdst + (uint32_t)(row * AT_STR + c * 4) * 4u,
                       __cvta_generic_to_global(K + hb + (size_t)row * D_MODEL + c * 4));
        }
        CP_COMMIT();
    }
    // ---- V tile 0 into registers ----
    float vpre[16];
    {
        const float* Vb = V + hb;
#pragma unroll
        for (int it = 0; it < 16; it++) {
            int idx = tid + 256 * it;            // 0..4095
            int d = idx & 63, kp = idx >> 6;
            vpre[it] = __ldg(Vb + (size_t)kp * D_MODEL + d);
        }
    }

    // fragment lane mapping
    const int aj   = lane >> 3;
    const int arow = ((aj & 1) << 3) + (lane & 7);
    const int acol = (aj >> 1) << 2;
    const int brow = ((aj >> 1) << 3) + (lane & 7);
    const int bcol = (aj & 1) << 2;
    const int wq   = wid * 16;

    CP_WAIT1();            // Q group done (K0 may still be in flight)
    __syncthreads();

    // Preload Q fragments, scaled by (1/8)*log2(e), rounded to tf32
    const float QSCALE = 0.125f * 1.4426950408889634f;
    uint32_t qfr[8][4];
    {
        uint32_t qa = smem_u32(Qs + (wq + arow) * AT_STR + acol);
#pragma unroll
        for (int ks = 0; ks < 8; ks++) {
            ldsm_x4(qfr[ks], qa + ks * 32);
#pragma unroll
            for (int r = 0; r < 4; r++) {
                float f = __uint_as_float(qfr[ks][r]) * QSCALE;
                uint32_t u = __float_as_uint(f);
                cvt_tf32(u);
                qfr[ks][r] = u;
            }
        }
    }
    // Qs region reused as P (safe: Q held in regs; all threads pass loop-top sync)

    float* Ps = Qs;
    const uint32_t pLd  = smem_u32(Ps + (wq + arow) * AT_STR + acol);
    const uint32_t kHLB = smem_u32(sm + AKHL_OFF + brow * AT_STR + bcol);
    const uint32_t vHLB = smem_u32(sm + AVHL_OFF + brow * AT_STR + bcol);

    float oacc[8][4];
#pragma unroll
    for (int nt = 0; nt < 8; nt++)
#pragma unroll
        for (int r = 0; r < 4; r++) oacc[nt][r] = 0.f;
    float m0 = -INFINITY, m1 = -INFINITY, l0 = 0.f, l1 = 0.f;

    const int lr = lane >> 2;
    const int lc = (lane & 3) * 2;

    for (int kt = 0; kt < nkt; kt++) {
        const int buf = kt & 1;
        const int k0  = kt * 64;
        CP_WAIT0();            // Kraw[buf] resident
        __syncthreads();       // all warps done reading KHL/VHL of kt-1

        // ---- producer: pack Kraw -> KHL, vpre -> VHL (once per CTA) ----
        {
            const float* KR = sm + AKRAW_OFF(buf);
            uint32_t* KHL = reinterpret_cast<uint32_t*>(sm + AKHL_OFF);
#pragma unroll
            for (int i = 0; i < 4; i++) {
                int chunk = tid + 256 * i;
                int row = chunk >> 4, c = chunk & 15;
                int off = row * AT_STR + c * 4;
                float4 r = *reinterpret_cast<const float4*>(KR + off);
                uint4 pk;
                pk.x = bsplit_pack(r.x);
                pk.y = bsplit_pack(r.y);
                pk.z = bsplit_pack(r.z);
                pk.w = bsplit_pack(r.w);
                *reinterpret_cast<uint4*>(KHL + off) = pk;
            }
            uint32_t* VHL = reinterpret_cast<uint32_t*>(sm + AVHL_OFF);
#pragma unroll
            for (int it = 0; it < 16; it++) {
                int idx = tid + 256 * it;
                int d = idx & 63, kp = idx >> 6;
                VHL[d * AT_STR + kp] = bsplit_pack(vpre[it]);
            }
        }
        // ---- prefetch next K (cp.async) and V (regs) ----
        if (kt + 1 < nkt) {
            uint32_t kdst = smem_u32(sm + AKRAW_OFF(buf ^ 1));
            const float* Kg = K + hb + (size_t)(k0 + 64) * D_MODEL;
#pragma unroll
            for (int i = 0; i < 4; i++) {
                int chunk = tid + 256 * i;
                int row = chunk >> 4, c = chunk & 15;
                CP_ASYNC16(kdst + (uint32_t)(row * AT_STR + c * 4) * 4u,
                           __cvta_generic_to_global(Kg + (size_t)row * D_MODEL + c * 4));
            }
            CP_COMMIT();
            const float* Vg = V + hb + (size_t)(k0 + 64) * D_MODEL;
#pragma unroll
            for (int it = 0; it < 16; it++) {
                int idx = tid + 256 * it;
                int d = idx & 63, kp = idx >> 6;
                vpre[it] = __ldg(Vg + (size_t)kp * D_MODEL + d);
            }
        }
        __syncthreads();       // packed tiles visible to all warps

        // ---- S = Q K^T (unpack hi/lo from one ldsm) ----
        float sacc[8][4];
#pragma unroll
        for (int nt = 0; nt < 8; nt++)
#pragma unroll
            for (int r = 0; r < 4; r++) sacc[nt][r] = 0.f;

#pragma unroll
        for (int ks = 0; ks < 8; ks++) {
#pragma unroll
            for (int p = 0; p < 4; p++) {
                uint32_t kp4[4], khi[4], klo[4];
                ldsm_x4(kp4, kHLB + (uint32_t)(p * 16 * AT_STR * 4) + ks * 32);
#pragma unroll
                for (int r = 0; r < 4; r++) {
                    khi[r] = kp4[r] & 0xFFFF0000u;
                    klo[r] = kp4[r] << 16;
                }
                mma_tf32(sacc[2 * p],     qfr[ks], khi[0], khi[1]);
                mma_tf32(sacc[2 * p],     qfr[ks], klo[0], klo[1]);
                mma_tf32(sacc[2 * p + 1], qfr[ks], khi[2], khi[3]);
                mma_tf32(sacc[2 * p + 1], qfr[ks], klo[2], klo[3]);
            }
        }

        const int rg0 = q0 + wq + lr;
        if (kt >= 2 * qt) {      // only diagonal-crossing tiles
#pragma unroll
            for (int nt = 0; nt < 8; nt++) {
                int cb = k0 + nt * 8 + lc;
                if (cb     > rg0)     sacc[nt][0] = -1e30f;
                if (cb + 1 > rg0)     sacc[nt][1] = -1e30f;
                if (cb     > rg0 + 8) sacc[nt][2] = -1e30f;
                if (cb + 1 > rg0 + 8) sacc[nt][3] = -1e30f;
            }
        }

        // ---- online softmax (log2 domain) ----
        float mx0 = -1e30f, mx1 = -1e30f;
#pragma unroll
        for (int nt = 0; nt < 8; nt++) {
            mx0 = fmaxf(mx0, fmaxf(sacc[nt][0], sacc[nt][1]));
            mx1 = fmaxf(mx1, fmaxf(sacc[nt][2], sacc[nt][3]));
        }
        mx0 = fmaxf(mx0, __shfl_xor_sync(0xffffffffu, mx0, 1));
        mx0 = fmaxf(mx0, __shfl_xor_sync(0xffffffffu, mx0, 2));
        mx1 = fmaxf(mx1, __shfl_xor_sync(0xffffffffu, mx1, 1));
        mx1 = fmaxf(mx1, __shfl_xor_sync(0xffffffffu, mx1, 2));
        float mn0 = fmaxf(m0, mx0), mn1 = fmaxf(m1, mx1);
        float a0 = ex2(m0 - mn0), a1 = ex2(m1 - mn1);
        float rs0 = 0.f, rs1 = 0.f;
#pragma unroll
        for (int nt = 0; nt < 8; nt++) {
            float e0 = ex2(sacc[nt][0] - mn0);
            float e1 = ex2(sacc[nt][1] - mn0);
            float e2 = ex2(sacc[nt][2] - mn1);
            float e3 = ex2(sacc[nt][3] - mn1);
            sacc[nt][0] = e0; sacc[nt][1] = e1; sacc[nt][2] = e2; sacc[nt][3] = e3;
            rs0 += e0 + e1; rs1 += e2 + e3;
        }
        rs0 += __shfl_xor_sync(0xffffffffu, rs0, 1);
        rs0 += __shfl_xor_sync(0xffffffffu, rs0, 2);
        rs1 += __shfl_xor_sync(0xffffffffu, rs1, 1);
        rs1 += __shfl_xor_sync(0xffffffffu, rs1, 2);
        l0 = l0 * a0 + rs0; m0 = mn0;
        l1 = l1 * a1 + rs1; m1 = mn1;
#pragma unroll
        for (int nt = 0; nt < 8; nt++) {
            oacc[nt][0] *= a0; oacc[nt][1] *= a0;
            oacc[nt][2] *= a1; oacc[nt][3] *= a1;
        }

        // ---- stash P into smem (warp-local region) ----
        {
            float* pr0 = Ps + (wq + lr) * AT_STR + lc;
            float* pr1 = pr0 + 8 * AT_STR;
#pragma unroll
            for (int nt = 0; nt < 8; nt++) {
                *reinterpret_cast<float2*>(pr0 + nt * 8) = make_float2(sacc[nt][0], sacc[nt][1]);
                *reinterpret_cast<float2*>(pr1 + nt * 8) = make_float2(sacc[nt][2], sacc[nt][3]);
            }
        }
        __syncwarp();

        // ---- O += P V ----
#pragma unroll
        for (int ks = 0; ks < 8; ks++) {
            uint32_t pf[4];
            ldsm_x4(pf, pLd + ks * 32);
#pragma unroll
            for (int r = 0; r < 4; r++) cvt_tf32(pf[r]);
#pragma unroll
            for (int p = 0; p < 4; p++) {
                uint32_t vp4[4], vhi[4], vlo[4];
                ldsm_x4(vp4, vHLB + (uint32_t)(p * 16 * AT_STR * 4) + ks * 32);
#pragma unroll
                for (int r = 0; r < 4; r++) {
                    vhi[r] = vp4[r] & 0xFFFF0000u;
                    vlo[r] = vp4[r] << 16;
                }
                mma_tf32(oacc[2 * p],     pf, vhi[0], vhi[1]);
                mma_tf32(oacc[2 * p],     pf, vlo[0], vlo[1]);
                mma_tf32(oacc[2 * p + 1], pf, vhi[2], vhi[3]);
                mma_tf32(oacc[2 * p + 1], pf, vlo[2], vlo[3]);
            }
        }
    }

    // ---- epilogue ----
    const float i0 = 1.f / l0, i1 = 1.f / l1;
    const int row0 = q0 + wq + lr;
    float* Ob = O + (size_t)(b * SEQ + row0) * D_MODEL + (size_t)h * DH + lc;
#pragma unroll
    for (int nt = 0; nt < 8; nt++) {
        *reinterpret_cast<float2*>(Ob + nt * 8)
            = make_float2(oacc[nt][0] * i0, oacc[nt][1] * i0);
        *reinterpret_cast<float2*>(Ob + 8 * D_MODEL + nt * 8)
            = make_float2(oacc[nt][2] * i1, oacc[nt][3] * i1);
    }
}

// ---------------------------------------------------------------------------
extern "C" void kernel_launch(void* const* d_in, const int* in_sizes, int n_in,
                              void* d_out, int out_size)
{
    const float* x  = (const float*)d_in[0];
    const float* Wq = (const float*)d_in[1];
    const float* Wk = (const float*)d_in[2];
    const float* Wv = (const float*)d_in[3];
    const float* Wo = (const float*)d_in[4];
    float* out = (float*)d_out;

    float *q, *k, *v, *ctx;
    cudaGetSymbolAddress((void**)&q,   g_q);
    cudaGetSymbolAddress((void**)&k,   g_k);
    cudaGetSymbolAddress((void**)&v,   g_v);
    cudaGetSymbolAddress((void**)&ctx, g_ctx);

    cudaFuncSetAttribute(sgemm_mma, cudaFuncAttributeMaxDynamicSharedMemorySize, SMEM_BYTES);
    cudaFuncSetAttribute(attn_mma,  cudaFuncAttributeMaxDynamicSharedMemorySize, AT_SMEM_BYTES);

    dim3 gg(D_MODEL / BN, NTOK / BM);   // (8, 32)
    sgemm_mma<<<gg, 256, SMEM_BYTES>>>(x, Wq, q, NTOK, D_MODEL, D_MODEL);
    sgemm_mma<<<gg, 256, SMEM_BYTES>>>(x, Wk, k, NTOK, D_MODEL, D_MODEL);
    sgemm_mma<<<gg, 256, SMEM_BYTES>>>(x, Wv, v, NTOK, D_MODEL, D_MODEL);

    attn_mma<<<dim3(SEQ / 128, NH, BATCH), 256, AT_SMEM_BYTES>>>(q, k, v, ctx);

    sgemm_mma<<<gg, 256, SMEM_BYTES>>>(ctx, Wo, out, NTOK, D_MODEL, D_MODEL);
}

// round 7
// speedup vs baseline: 3.2761x; 1.0508x over previous
#include <cuda_runtime.h>
#include <math.h>
#include <stdint.h>

#define D_MODEL 1024
#define NH      16
#define DH      64
#define BATCH   2
#define SEQ     2048
#define NTOK    (BATCH * SEQ)   // 4096

// Scratch (device globals — no runtime allocation allowed)
__device__ float    g_q  [NTOK * D_MODEL];          // Q, pre-scaled by 0.125*log2(e)
__device__ uint32_t g_kp [NTOK * D_MODEL];          // K packed [hi_bf16|lo_bf16], [token][chan]
__device__ uint32_t g_vt [D_MODEL * NTOK];          // V^T packed, [chan][token]
__device__ float    g_ctx[NTOK * D_MODEL];

__device__ __forceinline__ uint32_t smem_u32(const void* p) {
    uint32_t a;
    asm("{ .reg .u64 t; cvta.to.shared.u64 t, %1; cvt.u32.u64 %0, t; }" : "=r"(a) : "l"(p));
    return a;
}
__device__ __forceinline__ void ldsm_x4(uint32_t (&r)[4], uint32_t addr) {
    asm volatile("ldmatrix.sync.aligned.m8n8.x4.shared.b16 {%0,%1,%2,%3}, [%4];"
                 : "=r"(r[0]), "=r"(r[1]), "=r"(r[2]), "=r"(r[3]) : "r"(addr));
}
__device__ __forceinline__ void cvt_tf32(uint32_t& x) {
    asm volatile("cvt.rna.tf32.f32 %0, %0;" : "+r"(x));
}
__device__ __forceinline__ void mma_tf32(float (&c)[4], const uint32_t a[4],
                                         uint32_t b0, uint32_t b1) {
    asm volatile(
        "mma.sync.aligned.m16n8k8.row.col.f32.tf32.tf32.f32 "
        "{%0,%1,%2,%3}, {%4,%5,%6,%7}, {%8,%9}, {%0,%1,%2,%3};"
        : "+f"(c[0]), "+f"(c[1]), "+f"(c[2]), "+f"(c[3])
        : "r"(a[0]), "r"(a[1]), "r"(a[2]), "r"(a[3]), "r"(b0), "r"(b1));
}
// bf16 two-term split packed into one word: [hi_bf16 (31:16) | lo_bf16 (15:0)]
__device__ __forceinline__ uint32_t bsplit_pack(float x) {
    uint32_t r;
    asm("{.reg .b16 h, l, z;\n\t"
        ".reg .f32 hf, lf;\n\t"
        "mov.b16 z, 0;\n\t"
        "cvt.rn.bf16.f32 h, %1;\n\t"
        "mov.b32 hf, {z, h};\n\t"
        "sub.f32 lf, %1, hf;\n\t"
        "cvt.rn.bf16.f32 l, lf;\n\t"
        "mov.b32 %0, {l, h};\n\t}"
        : "=r"(r) : "f"(x));
    return r;
}
__device__ __forceinline__ float ex2(float x) {
    float y; asm("ex2.approx.f32 %0, %1;" : "=f"(y) : "f"(x)); return y;
}
#define CP_ASYNC16(dst, src) \
    asm volatile("cp.async.cg.shared.global [%0], [%1], 16;" :: "r"(dst), "l"(src) : "memory")
#define CP_COMMIT() asm volatile("cp.async.commit_group;" ::: "memory")
#define CP_WAIT0()  asm volatile("cp.async.wait_group 0;" ::: "memory")
#define CP_WAIT1()  asm volatile("cp.async.wait_group 1;" ::: "memory")

// ============================================================================
// TF32 tensor-core GEMM: C[M,N] = A[M,K] @ W[N,K]^T  (row-major, K contiguous)
// MODE 0: plain fp32 out; MODE 1: fp32 out scaled by QSCALE; MODE 2: packed
// bf16 hi|lo words out. launch_bounds(256,2) -> 2 CTA/SM, one wave.
// ============================================================================
#define BM 128
#define BN 128
#define BK 32
#define KSTR 36
#define TILE_F (BM * KSTR)
#define SMEM_FLOATS (4 * TILE_F)
#define SMEM_BYTES (SMEM_FLOATS * 4)

#define QSCALEF (0.125f * 1.4426950408889634f)

template <int MODE>
__global__ __launch_bounds__(256, 2) void sgemm_mma(
    const float* __restrict__ A, const float* __restrict__ W,
    void* __restrict__ Cv, int M, int N, int K)
{
    extern __shared__ float sm[];
    float* AsP[2] = { sm,              sm + TILE_F };
    float* BsP[2] = { sm + 2 * TILE_F, sm + 3 * TILE_F };

    const int tid  = threadIdx.x;
    const int wid  = tid >> 5;
    const int lane = tid & 31;
    const int bm   = blockIdx.y * BM;
    const int bn   = blockIdx.x * BN;
    const int wm = (wid >> 2) * 64;
    const int wn = (wid & 3) * 32;

    float acc[4][4][4];
#pragma unroll
    for (int i = 0; i < 4; i++)
#pragma unroll
        for (int j = 0; j < 4; j++)
#pragma unroll
            for (int q = 0; q < 4; q++) acc[i][j][q] = 0.f;

    const int aj = lane >> 3;
    const int arow = ((aj & 1) << 3) + (lane & 7);
    const int acol = (aj >> 1) << 2;
    const int brow = ((aj >> 1) << 3) + (lane & 7);
    const int bcol = (aj & 1) << 2;

    // base addresses only (offsets are compile-time) to save registers
    uint32_t aBase[2], bBase[2];
#pragma unroll
    for (int buf = 0; buf < 2; buf++) {
        aBase[buf] = smem_u32(AsP[buf] + (wm + arow) * KSTR + acol);
        bBase[buf] = smem_u32(BsP[buf] + (wn + brow) * KSTR + bcol);
    }

    const float* Ap = A + (size_t)bm * K;
    const float* Wp = W + (size_t)bn * K;
    const int KT = K / BK;

    auto load_tile = [&](int t, int buf) {
        const float* Ag = Ap + t * BK;
        const float* Bg = Wp + t * BK;
        uint32_t sa = smem_u32(AsP[buf]);
        uint32_t sb = smem_u32(BsP[buf]);
#pragma unroll
        for (int i = 0; i < 4; i++) {
            int chunk = tid + 256 * i;
            int row = chunk >> 3;
            int c   = chunk & 7;
            uint32_t so = (uint32_t)(row * KSTR + c * 4) * 4u;
            CP_ASYNC16(sa + so, __cvta_generic_to_global(Ag + (size_t)row * K + c * 4));
            CP_ASYNC16(sb + so, __cvta_generic_to_global(Bg + (size_t)row * K + c * 4));
        }
        CP_COMMIT();
    };

    load_tile(0, 0);

    for (int t = 0; t < KT; t++) {
        const int buf = t & 1;
        if (t + 1 < KT) { load_tile(t + 1, buf ^ 1); CP_WAIT1(); }
        else           { CP_WAIT0(); }
        __syncthreads();

#pragma unroll
        for (int ks = 0; ks < 4; ks++) {
            uint32_t afr[4][4], bfr[2][4];
#pragma unroll
            for (int mt = 0; mt < 4; mt++)
                ldsm_x4(afr[mt], aBase[buf] + (uint32_t)(mt * 16 * KSTR * 4) + ks * 32);
#pragma unroll
            for (int p = 0; p < 2; p++)
                ldsm_x4(bfr[p], bBase[buf] + (uint32_t)(p * 16 * KSTR * 4) + ks * 32);
#pragma unroll
            for (int mt = 0; mt < 4; mt++)
#pragma unroll
                for (int q = 0; q < 4; q++) cvt_tf32(afr[mt][q]);
#pragma unroll
            for (int p = 0; p < 2; p++)
#pragma unroll
                for (int q = 0; q < 4; q++) cvt_tf32(bfr[p][q]);
#pragma unroll
            for (int mt = 0; mt < 4; mt++)
#pragma unroll
                for (int nt = 0; nt < 4; nt++)
                    mma_tf32(acc[mt][nt], afr[mt], bfr[nt >> 1][(nt & 1) * 2],
                             bfr[nt >> 1][(nt & 1) * 2 + 1]);
        }
        __syncthreads();
    }

    const int rr = lane >> 2;
    const int cc = (lane & 3) * 2;
#pragma unroll
    for (int mt = 0; mt < 4; mt++) {
#pragma unroll
        for (int nt = 0; nt < 4; nt++) {
            int row = bm + wm + mt * 16 + rr;
            int col = bn + wn + nt * 8 + cc;
            if (MODE == 2) {
                uint32_t* Cp = (uint32_t*)Cv;
                uint2 v0 = make_uint2(bsplit_pack(acc[mt][nt][0]), bsplit_pack(acc[mt][nt][1]));
                uint2 v1 = make_uint2(bsplit_pack(acc[mt][nt][2]), bsplit_pack(acc[mt][nt][3]));
                *reinterpret_cast<uint2*>(Cp + (size_t)row * N + col)       = v0;
                *reinterpret_cast<uint2*>(Cp + (size_t)(row + 8) * N + col) = v1;
            } else {
                const float s = (MODE == 1) ? QSCALEF : 1.0f;
                float* Cp = (float*)Cv;
                *reinterpret_cast<float2*>(Cp + (size_t)row * N + col)
                    = make_float2(acc[mt][nt][0] * s, acc[mt][nt][1] * s);
                *reinterpret_cast<float2*>(Cp + (size_t)(row + 8) * N + col)
                    = make_float2(acc[mt][nt][2] * s, acc[mt][nt][3] * s);
            }
        }
    }
}

// ============================================================================
// Tensor-core causal flash attention, tf32 mma.sync.
// R7: K/V arrive PRE-PACKED (bf16 hi|lo) from the GEMM epilogues; V arrives
// pre-transposed. No producer stage, one __syncthreads per ktile, double-
// buffered packed tiles loaded by cp.async.
// smem (words): Q/P 8704 | KHL x2 8704 | VHL x2 8704 = 26112 (102 KB)
// ============================================================================
#define AT_STR 68
#define AQS_OFF   0
#define AKHL_OFF(b) (8704  + (b) * 4352)
#define AVHL_OFF(b) (17408 + (b) * 4352)
#define AT_SMEM_WORDS 26112
#define AT_SMEM_BYTES (AT_SMEM_WORDS * 4)   // 104448

__global__ __launch_bounds__(256, 1) void attn_mma(
    const float* __restrict__ Q, const uint32_t* __restrict__ Kp,
    const uint32_t* __restrict__ Vt, float* __restrict__ O)
{
    extern __shared__ float sm[];
    const int tid  = threadIdx.x;
    const int wid  = tid >> 5;
    const int lane = tid & 31;
    const int qt   = (SEQ / 128 - 1) - blockIdx.x;   // long blocks first
    const int h    = blockIdx.y;
    const int b    = blockIdx.z;
    const int q0   = qt * 128;
    const int nkt  = 2 * qt + 2;
    const size_t hb = (size_t)b * SEQ * D_MODEL + (size_t)h * DH;

    float* Qs = sm + AQS_OFF;

    // ---- load a packed K tile (64 tokens x 64 words) into KHL[buf] ----
    auto load_k = [&](int kt, int buf) {
        uint32_t dst = smem_u32(sm + AKHL_OFF(buf));
        const uint32_t* Kg = Kp + hb + (size_t)kt * 64 * D_MODEL;
#pragma unroll
        for (int i = 0; i < 4; i++) {
            int chunk = tid + 256 * i;           // 0..1023
            int row = chunk >> 4, c = chunk & 15;
            CP_ASYNC16(dst + (uint32_t)(row * AT_STR + c * 4) * 4u,
                       __cvta_generic_to_global(Kg + (size_t)row * D_MODEL + c * 4));
        }
    };
    // ---- load a packed V^T tile (64 d-rows x 64 s-words) into VHL[buf] ----
    auto load_v = [&](int kt, int buf) {
        uint32_t dst = smem_u32(sm + AVHL_OFF(buf));
        const uint32_t* Vg = Vt + (size_t)h * 64 * NTOK + (size_t)b * SEQ + (size_t)kt * 64;
#pragma unroll
        for (int i = 0; i < 4; i++) {
            int chunk = tid + 256 * i;
            int d = chunk >> 4, c = chunk & 15;
            CP_ASYNC16(dst + (uint32_t)(d * AT_STR + c * 4) * 4u,
                       __cvta_generic_to_global(Vg + (size_t)d * NTOK + c * 4));
        }
    };

    // ---- prologue: Q (group0), K0+V0 (group1) ----
    {
        uint32_t qdst = smem_u32(Qs);
#pragma unroll
        for (int i = 0; i < 8; i++) {
            int chunk = tid + 256 * i;           // 0..2047
            int row = chunk >> 4, c = chunk & 15;
            CP_ASYNC16(qdst + (uint32_t)(row * AT_STR + c * 4) * 4u,
                       __cvta_generic_to_global(Q + hb + (size_t)(q0 + row) * D_MODEL + c * 4));
        }
        CP_COMMIT();
    }
    load_k(0, 0);
    load_v(0, 0);
    CP_COMMIT();

    // fragment lane mapping
    const int aj   = lane >> 3;
    const int arow = ((aj & 1) << 3) + (lane & 7);
    const int acol = (aj >> 1) << 2;
    const int brow = ((aj >> 1) << 3) + (lane & 7);
    const int bcol = (aj & 1) << 2;
    const int wq   = wid * 16;

    CP_WAIT1();            // Q resident (K0/V0 may be in flight)
    __syncthreads();

    // Preload Q fragments (already pre-scaled in the GEMM epilogue)
    uint32_t qfr[8][4];
    {
        uint32_t qa = smem_u32(Qs + (wq + arow) * AT_STR + acol);
#pragma unroll
        for (int ks = 0; ks < 8; ks++) {
            ldsm_x4(qfr[ks], qa + ks * 32);
#pragma unroll
            for (int r = 0; r < 4; r++) cvt_tf32(qfr[ks][r]);
        }
    }
    // Qs region reused as P (safe: Q in regs; all threads pass loop-top sync)

    float* Ps = Qs;
    const uint32_t pLd = smem_u32(Ps + (wq + arow) * AT_STR + acol);
    const uint32_t kHLB[2] = { smem_u32(sm + AKHL_OFF(0) + brow * AT_STR + bcol),
                               smem_u32(sm + AKHL_OFF(1) + brow * AT_STR + bcol) };
    const uint32_t vHLB[2] = { smem_u32(sm + AVHL_OFF(0) + brow * AT_STR + bcol),
                               smem_u32(sm + AVHL_OFF(1) + brow * AT_STR + bcol) };

    float oacc[8][4];
#pragma unroll
    for (int nt = 0; nt < 8; nt++)
#pragma unroll
        for (int r = 0; r < 4; r++) oacc[nt][r] = 0.f;
    float m0 = -INFINITY, m1 = -INFINITY, l0 = 0.f, l1 = 0.f;

    const int lr = lane >> 2;
    const int lc = (lane & 3) * 2;

    for (int kt = 0; kt < nkt; kt++) {
        const int buf = kt & 1;
        const int k0  = kt * 64;
        CP_WAIT0();            // KHL/VHL[buf] resident
        __syncthreads();       // everyone done with [buf^1] from kt-1

        // prefetch next tiles into [buf^1] (overlaps all mma work below)
        if (kt + 1 < nkt) {
            load_k(kt + 1, buf ^ 1);
            load_v(kt + 1, buf ^ 1);
            CP_COMMIT();
        }

        // ---- S = Q K^T (unpack hi/lo from one ldsm) ----
        float sacc[8][4];
#pragma unroll
        for (int nt = 0; nt < 8; nt++)
#pragma unroll
            for (int r = 0; r < 4; r++) sacc[nt][r] = 0.f;

#pragma unroll
        for (int ks = 0; ks < 8; ks++) {
#pragma unroll
            for (int p = 0; p < 4; p++) {
                uint32_t kp4[4], khi[4], klo[4];
                ldsm_x4(kp4, kHLB[buf] + (uint32_t)(p * 16 * AT_STR * 4) + ks * 32);
#pragma unroll
                for (int r = 0; r < 4; r++) {
                    khi[r] = kp4[r] & 0xFFFF0000u;
                    klo[r] = kp4[r] << 16;
                }
                mma_tf32(sacc[2 * p],     qfr[ks], khi[0], khi[1]);
                mma_tf32(sacc[2 * p],     qfr[ks], klo[0], klo[1]);
                mma_tf32(sacc[2 * p + 1], qfr[ks], khi[2], khi[3]);
                mma_tf32(sacc[2 * p + 1], qfr[ks], klo[2], klo[3]);
            }
        }

        const int rg0 = q0 + wq + lr;
        if (kt >= 2 * qt) {      // only diagonal-crossing tiles
#pragma unroll
            for (int nt = 0; nt < 8; nt++) {
                int cb = k0 + nt * 8 + lc;
                if (cb     > rg0)     sacc[nt][0] = -1e30f;
                if (cb + 1 > rg0)     sacc[nt][1] = -1e30f;
                if (cb     > rg0 + 8) sacc[nt][2] = -1e30f;
                if (cb + 1 > rg0 + 8) sacc[nt][3] = -1e30f;
            }
        }

        // ---- online softmax (log2 domain) ----
        float mx0 = -1e30f, mx1 = -1e30f;
#pragma unroll
        for (int nt = 0; nt < 8; nt++) {
            mx0 = fmaxf(mx0, fmaxf(sacc[nt][0], sacc[nt][1]));
            mx1 = fmaxf(mx1, fmaxf(sacc[nt][2], sacc[nt][3]));
        }
        mx0 = fmaxf(mx0, __shfl_xor_sync(0xffffffffu, mx0, 1));
        mx0 = fmaxf(mx0, __shfl_xor_sync(0xffffffffu, mx0, 2));
        mx1 = fmaxf(mx1, __shfl_xor_sync(0xffffffffu, mx1, 1));
        mx1 = fmaxf(mx1, __shfl_xor_sync(0xffffffffu, mx1, 2));
        float mn0 = fmaxf(m0, mx0), mn1 = fmaxf(m1, mx1);
        float a0 = ex2(m0 - mn0), a1 = ex2(m1 - mn1);
        float rs0 = 0.f, rs1 = 0.f;
#pragma unroll
        for (int nt = 0; nt < 8; nt++) {
            float e0 = ex2(sacc[nt][0] - mn0);
            float e1 = ex2(sacc[nt][1] - mn0);
            float e2 = ex2(sacc[nt][2] - mn1);
            float e3 = ex2(sacc[nt][3] - mn1);
            sacc[nt][0] = e0; sacc[nt][1] = e1; sacc[nt][2] = e2; sacc[nt][3] = e3;
            rs0 += e0 + e1; rs1 += e2 + e3;
        }
        rs0 += __shfl_xor_sync(0xffffffffu, rs0, 1);
        rs0 += __shfl_xor_sync(0xffffffffu, rs0, 2);
        rs1 += __shfl_xor_sync(0xffffffffu, rs1, 1);
        rs1 += __shfl_xor_sync(0xffffffffu, rs1, 2);
        l0 = l0 * a0 + rs0; m0 = mn0;
        l1 = l1 * a1 + rs1; m1 = mn1;
#pragma unroll
        for (int nt = 0; nt < 8; nt++) {
            oacc[nt][0] *= a0; oacc[nt][1] *= a0;
            oacc[nt][2] *= a1; oacc[nt][3] *= a1;
        }

        // ---- stash P into smem (warp-local region) ----
        {
            float* pr0 = Ps + (wq + lr) * AT_STR + lc;
            float* pr1 = pr0 + 8 * AT_STR;
#pragma unroll
            for (int nt = 0; nt < 8; nt++) {
                *reinterpret_cast<float2*>(pr0 + nt * 8) = make_float2(sacc[nt][0], sacc[nt][1]);
                *reinterpret_cast<float2*>(pr1 + nt * 8) = make_float2(sacc[nt][2], sacc[nt][3]);
            }
        }
        __syncwarp();

        // ---- O += P V ----
#pragma unroll
        for (int ks = 0; ks < 8; ks++) {
            uint32_t pf[4];
            ldsm_x4(pf, pLd + ks * 32);
#pragma unroll
            for (int r = 0; r < 4; r++) cvt_tf32(pf[r]);
#pragma unroll
            for (int p = 0; p < 4; p++) {
                uint32_t vp4[4], vhi[4], vlo[4];
                ldsm_x4(vp4, vHLB[buf] + (uint32_t)(p * 16 * AT_STR * 4) + ks * 32);
#pragma unroll
                for (int r = 0; r < 4; r++) {
                    vhi[r] = vp4[r] & 0xFFFF0000u;
                    vlo[r] = vp4[r] << 16;
                }
                mma_tf32(oacc[2 * p],     pf, vhi[0], vhi[1]);
                mma_tf32(oacc[2 * p],     pf, vlo[0], vlo[1]);
                mma_tf32(oacc[2 * p + 1], pf, vhi[2], vhi[3]);
                mma_tf32(oacc[2 * p + 1], pf, vlo[2], vlo[3]);
            }
        }
    }

    // ---- epilogue ----
    const float i0 = 1.f / l0, i1 = 1.f / l1;
    const int row0 = q0 + wq + lr;
    float* Ob = O + (size_t)(b * SEQ + row0) * D_MODEL + (size_t)h * DH + lc;
#pragma unroll
    for (int nt = 0; nt < 8; nt++) {
        *reinterpret_cast<float2*>(Ob + nt * 8)
            = make_float2(oacc[nt][0] * i0, oacc[nt][1] * i0);
        *reinterpret_cast<float2*>(Ob + 8 * D_MODEL + nt * 8)
            = make_float2(oacc[nt][2] * i1, oacc[nt][3] * i1);
    }
}

// ---------------------------------------------------------------------------
extern "C" void kernel_launch(void* const* d_in, const int* in_sizes, int n_in,
                              void* d_out, int out_size)
{
    const float* x  = (const float*)d_in[0];
    const float* Wq = (const float*)d_in[1];
    const float* Wk = (const float*)d_in[2];
    const float* Wv = (const float*)d_in[3];
    const float* Wo = (const float*)d_in[4];
    float* out = (float*)d_out;

    float *q, *ctx;
    uint32_t *kp, *vt;
    cudaGetSymbolAddress((void**)&q,   g_q);
    cudaGetSymbolAddress((void**)&kp,  g_kp);
    cudaGetSymbolAddress((void**)&vt,  g_vt);
    cudaGetSymbolAddress((void**)&ctx, g_ctx);

    cudaFuncSetAttribute(sgemm_mma<0>, cudaFuncAttributeMaxDynamicSharedMemorySize, SMEM_BYTES);
    cudaFuncSetAttribute(sgemm_mma<1>, cudaFuncAttributeMaxDynamicSharedMemorySize, SMEM_BYTES);
    cudaFuncSetAttribute(sgemm_mma<2>, cudaFuncAttributeMaxDynamicSharedMemorySize, SMEM_BYTES);
    cudaFuncSetAttribute(attn_mma,     cudaFuncAttributeMaxDynamicSharedMemorySize, AT_SMEM_BYTES);

    dim3 gg (D_MODEL / BN, NTOK / BM);   // (8, 32)  — token-major outputs
    dim3 ggT(NTOK / BN, D_MODEL / BM);   // (32, 8)  — V^T output

    sgemm_mma<1><<<gg,  256, SMEM_BYTES>>>(x,  Wq, (void*)q,   NTOK,    D_MODEL, D_MODEL);
    sgemm_mma<2><<<gg,  256, SMEM_BYTES>>>(x,  Wk, (void*)kp,  NTOK,    D_MODEL, D_MODEL);
    sgemm_mma<2><<<ggT, 256, SMEM_BYTES>>>(Wv, x,  (void*)vt,  D_MODEL, NTOK,    D_MODEL);

    attn_mma<<<dim3(SEQ / 128, NH, BATCH), 256, AT_SMEM_BYTES>>>(q, kp, vt, ctx);

    sgemm_mma<0><<<gg, 256, SMEM_BYTES>>>(ctx, Wo, (void*)out, NTOK, D_MODEL, D_MODEL);
}

// round 8
// speedup vs baseline: 6.4372x; 1.9649x over previous
#include <cuda_runtime.h>
#include <cuda_fp16.h>
#include <math.h>
#include <stdint.h>

#define D_MODEL 1024
#define NH      16
#define DH      64
#define BATCH   2
#define SEQ     2048
#define NTOK    (BATCH * SEQ)   // 4096

// Scratch (device globals — no runtime allocation allowed)
__device__ __half g_xh [NTOK * D_MODEL];       // x in fp16
__device__ __half g_wqh[D_MODEL * D_MODEL];
__device__ __half g_wkh[D_MODEL * D_MODEL];
__device__ __half g_wvh[D_MODEL * D_MODEL];
__device__ __half g_woh[D_MODEL * D_MODEL];
__device__ __half g_q16 [NTOK * D_MODEL];      // Q fp16, pre-scaled by 0.125*log2(e)
__device__ __half g_k16 [NTOK * D_MODEL];      // K fp16 [token][chan]
__device__ __half g_vt16[D_MODEL * NTOK];      // V^T fp16 [chan][token]
__device__ __half g_ctx [NTOK * D_MODEL];      // attention output fp16

__device__ __forceinline__ uint32_t smem_u32(const void* p) {
    uint32_t a;
    asm("{ .reg .u64 t; cvta.to.shared.u64 t, %1; cvt.u32.u64 %0, t; }" : "=r"(a) : "l"(p));
    return a;
}
__device__ __forceinline__ void ldsm_x4(uint32_t (&r)[4], uint32_t addr) {
    asm volatile("ldmatrix.sync.aligned.m8n8.x4.shared.b16 {%0,%1,%2,%3}, [%4];"
                 : "=r"(r[0]), "=r"(r[1]), "=r"(r[2]), "=r"(r[3]) : "r"(addr));
}
// fp16 mma with fp32 accumulate
__device__ __forceinline__ void mma_f16(float (&c)[4], const uint32_t a[4],
                                        uint32_t b0, uint32_t b1) {
    asm volatile(
        "mma.sync.aligned.m16n8k16.row.col.f32.f16.f16.f32 "
        "{%0,%1,%2,%3}, {%4,%5,%6,%7}, {%8,%9}, {%0,%1,%2,%3};"
        : "+f"(c[0]), "+f"(c[1]), "+f"(c[2]), "+f"(c[3])
        : "r"(a[0]), "r"(a[1]), "r"(a[2]), "r"(a[3]), "r"(b0), "r"(b1));
}
__device__ __forceinline__ float ex2(float x) {
    float y; asm("ex2.approx.f32 %0, %1;" : "=f"(y) : "f"(x)); return y;
}
#define CP_ASYNC16(dst, src) \
    asm volatile("cp.async.cg.shared.global [%0], [%1], 16;" :: "r"(dst), "l"(src) : "memory")
#define CP_COMMIT() asm volatile("cp.async.commit_group;" ::: "memory")
#define CP_WAIT0()  asm volatile("cp.async.wait_group 0;" ::: "memory")
#define CP_WAIT1()  asm volatile("cp.async.wait_group 1;" ::: "memory")

// ============================================================================
// fp32 -> fp16 conversion (vectorized). n must be divisible by 1024.
// ============================================================================
__global__ __launch_bounds__(256) void f2h(const float* __restrict__ in,
                                           __half* __restrict__ out, int n)
{
    int i = (blockIdx.x * 256 + threadIdx.x) * 4;
    if (i < n) {
        float4 v = *reinterpret_cast<const float4*>(in + i);
        __half2 h0 = __floats2half2_rn(v.x, v.y);
        __half2 h1 = __floats2half2_rn(v.z, v.w);
        uint2 pk = make_uint2(*reinterpret_cast<uint32_t*>(&h0),
                              *reinterpret_cast<uint32_t*>(&h1));
        *reinterpret_cast<uint2*>(out + i) = pk;
    }
}

// ============================================================================
// fp16 tensor-core GEMM: C[M,N] = A[M,K] @ W[N,K]^T  (both fp16 row-major)
// CTA 128x128, BK=64, 256 threads = 8 warps (2x4), warp tile 64x32.
// MODE 0: fp32 out; MODE 1: fp16 out * QSCALE; MODE 2: fp16 out.
// ============================================================================
#define BM 128
#define BN 128
#define BKH 64
#define KSTRH 72                         // fp16 elems per smem row (144 B)
#define TILE_H (BM * KSTRH)              // fp16 per operand tile = 9216
#define GSMEM_BYTES (4 * TILE_H * 2)     // 73728

#define QSCALEF (0.125f * 1.4426950408889634f)

template <int MODE>
__global__ __launch_bounds__(256, 2) void hgemm(
    const __half* __restrict__ A, const __half* __restrict__ W,
    void* __restrict__ Cv, int M, int N, int K)
{
    extern __shared__ __half smh[];
    __half* AsP[2] = { smh,              smh + TILE_H };
    __half* BsP[2] = { smh + 2 * TILE_H, smh + 3 * TILE_H };

    const int tid  = threadIdx.x;
    const int wid  = tid >> 5;
    const int lane = tid & 31;
    const int bm   = blockIdx.y * BM;
    const int bn   = blockIdx.x * BN;
    const int wm = (wid >> 2) * 64;
    const int wn = (wid & 3) * 32;

    float acc[4][4][4];
#pragma unroll
    for (int i = 0; i < 4; i++)
#pragma unroll
        for (int j = 0; j < 4; j++)
#pragma unroll
            for (int q = 0; q < 4; q++) acc[i][j][q] = 0.f;

    // ldmatrix lane mapping: matrices j0=rows0-7/+0B, j1=rows8-15/+0B,
    // j2=rows0-7/+16B, j3=rows8-15/+16B
    const int aj   = lane >> 3;
    const int mrow = ((aj & 1) << 3) + (lane & 7);
    const int mcol = (aj >> 1) << 4;      // byte offset 0 or 16

    uint32_t aBase[2], bBase[2];
#pragma unroll
    for (int buf = 0; buf < 2; buf++) {
        aBase[buf] = smem_u32(AsP[buf]) + (uint32_t)(wm + mrow) * (KSTRH * 2) + mcol;
        bBase[buf] = smem_u32(BsP[buf]) + (uint32_t)(wn + mrow) * (KSTRH * 2) + mcol;
    }

    const __half* Ap = A + (size_t)bm * K;
    const __half* Wp = W + (size_t)bn * K;
    const int KT = K / BKH;   // 16

    auto load_tile = [&](int t, int buf) {
        const __half* Ag = Ap + t * BKH;
        const __half* Bg = Wp + t * BKH;
        uint32_t sa = smem_u32(AsP[buf]);
        uint32_t sb = smem_u32(BsP[buf]);
#pragma unroll
        for (int i = 0; i < 4; i++) {
            int chunk = tid + 256 * i;       // 0..1023
            int row = chunk >> 3;
            int c   = chunk & 7;             // 16B chunk within 128B row
            uint32_t so = (uint32_t)row * (KSTRH * 2) + c * 16;
            CP_ASYNC16(sa + so, __cvta_generic_to_global(Ag + (size_t)row * K + c * 8));
            CP_ASYNC16(sb + so, __cvta_generic_to_global(Bg + (size_t)row * K + c * 8));
        }
        CP_COMMIT();
    };

    load_tile(0, 0);

    for (int t = 0; t < KT; t++) {
        const int buf = t & 1;
        if (t + 1 < KT) { load_tile(t + 1, buf ^ 1); CP_WAIT1(); }
        else           { CP_WAIT0(); }
        __syncthreads();

#pragma unroll
        for (int ks = 0; ks < 4; ks++) {          // 4 x k16 per BK=64
            uint32_t afr[4][4], bfr[2][4];
#pragma unroll
            for (int mt = 0; mt < 4; mt++)
                ldsm_x4(afr[mt], aBase[buf] + (uint32_t)(mt * 16 * KSTRH * 2) + ks * 32);
#pragma unroll
            for (int p = 0; p < 2; p++)
                ldsm_x4(bfr[p], bBase[buf] + (uint32_t)(p * 16 * KSTRH * 2) + ks * 32);
#pragma unroll
            for (int mt = 0; mt < 4; mt++) {
#pragma unroll
                for (int p = 0; p < 2; p++) {
                    // n0-7 of group p: (r0, r2); n8-15: (r1, r3)
                    mma_f16(acc[mt][2 * p],     afr[mt], bfr[p][0], bfr[p][2]);
                    mma_f16(acc[mt][2 * p + 1], afr[mt], bfr[p][1], bfr[p][3]);
                }
            }
        }
        __syncthreads();
    }

    const int rr = lane >> 2;
    const int cc = (lane & 3) * 2;
#pragma unroll
    for (int mt = 0; mt < 4; mt++) {
#pragma unroll
        for (int nt = 0; nt < 4; nt++) {
            int row = bm + wm + mt * 16 + rr;
            int col = bn + wn + nt * 8 + cc;
            if (MODE == 0) {
                float* Cp = (float*)Cv;
                *reinterpret_cast<float2*>(Cp + (size_t)row * N + col)
                    = make_float2(acc[mt][nt][0], acc[mt][nt][1]);
                *reinterpret_cast<float2*>(Cp + (size_t)(row + 8) * N + col)
                    = make_float2(acc[mt][nt][2], acc[mt][nt][3]);
            } else {
                const float s = (MODE == 1) ? QSCALEF : 1.0f;
                __half* Cp = (__half*)Cv;
                __half2 v0 = __floats2half2_rn(acc[mt][nt][0] * s, acc[mt][nt][1] * s);
                __half2 v1 = __floats2half2_rn(acc[mt][nt][2] * s, acc[mt][nt][3] * s);
                *reinterpret_cast<__half2*>(Cp + (size_t)row * N + col)       = v0;
                *reinterpret_cast<__half2*>(Cp + (size_t)(row + 8) * N + col) = v1;
            }
        }
    }
}

// ============================================================================
// fp16 tensor-core causal flash attention (m16n8k16).
// BQ=128 q-rows/CTA, 8 warps x 16 rows; k-tiles of 64 tokens.
// Q/K/V^T arrive in fp16 from the GEMM epilogues (Q pre-scaled).
// smem: Q/P [128][72] fp16 | K x2 [64][72] | V^T x2 [64][72] = 54 KB -> 2 CTA/SM
// ============================================================================
#define ASTRH 72
#define AQ_OFF    0                          // fp16 index
#define AK_OFF(b) (128 * ASTRH + (b) * 64 * ASTRH)
#define AV_OFF(b) (128 * ASTRH + 2 * 64 * ASTRH + (b) * 64 * ASTRH)
#define AT_H      (128 * ASTRH + 4 * 64 * ASTRH)
#define AT_BYTES  (AT_H * 2)                 // 55296

__global__ __launch_bounds__(256, 2) void attn_mma(
    const __half* __restrict__ Q, const __half* __restrict__ Kp,
    const __half* __restrict__ Vt, __half* __restrict__ O)
{
    extern __shared__ __half smh[];
    const int tid  = threadIdx.x;
    const int wid  = tid >> 5;
    const int lane = tid & 31;
    const int qt   = (SEQ / 128 - 1) - blockIdx.x;   // long blocks first
    const int h    = blockIdx.y;
    const int b    = blockIdx.z;
    const int q0   = qt * 128;
    const int nkt  = 2 * qt + 2;
    const size_t hb = (size_t)b * SEQ * D_MODEL + (size_t)h * DH;

    auto load_k = [&](int kt, int buf) {
        uint32_t dst = smem_u32(smh + AK_OFF(buf));
        const __half* Kg = Kp + hb + (size_t)kt * 64 * D_MODEL;
#pragma unroll
        for (int i = 0; i < 2; i++) {
            int chunk = tid + 256 * i;       // 0..511
            int row = chunk >> 3, c = chunk & 7;
            CP_ASYNC16(dst + (uint32_t)row * (ASTRH * 2) + c * 16,
                       __cvta_generic_to_global(Kg + (size_t)row * D_MODEL + c * 8));
        }
    };
    auto load_v = [&](int kt, int buf) {
        uint32_t dst = smem_u32(smh + AV_OFF(buf));
        const __half* Vg = Vt + (size_t)h * 64 * NTOK + (size_t)b * SEQ + (size_t)kt * 64;
#pragma unroll
        for (int i = 0; i < 2; i++) {
            int chunk = tid + 256 * i;
            int d = chunk >> 3, c = chunk & 7;
            CP_ASYNC16(dst + (uint32_t)d * (ASTRH * 2) + c * 16,
                       __cvta_generic_to_global(Vg + (size_t)d * NTOK + c * 8));
        }
    };

    // prologue: Q (group0), K0+V0 (group1)
    {
        uint32_t qdst = smem_u32(smh + AQ_OFF);
#pragma unroll
        for (int i = 0; i < 4; i++) {
            int chunk = tid + 256 * i;       // 0..1023
            int row = chunk >> 3, c = chunk & 7;
            CP_ASYNC16(qdst + (uint32_t)row * (ASTRH * 2) + c * 16,
                       __cvta_generic_to_global(Q + hb + (size_t)(q0 + row) * D_MODEL + c * 8));
        }
        CP_COMMIT();
    }
    load_k(0, 0);
    load_v(0, 0);
    CP_COMMIT();

    const int aj   = lane >> 3;
    const int mrow = ((aj & 1) << 3) + (lane & 7);
    const int mcol = (aj >> 1) << 4;
    const int wq   = wid * 16;

    CP_WAIT1();
    __syncthreads();

    // Preload Q fragments (pre-scaled in GEMM epilogue): 4 k16-steps
    uint32_t qfr[4][4];
    {
        uint32_t qa = smem_u32(smh + AQ_OFF) + (uint32_t)(wq + mrow) * (ASTRH * 2) + mcol;
#pragma unroll
        for (int ks = 0; ks < 4; ks++) ldsm_x4(qfr[ks], qa + ks * 32);
    }
    // Q smem region reused as P (all threads hold Q frags; pass loop-top sync)

    __half* Ps = smh + AQ_OFF;
    const uint32_t pLd = smem_u32(Ps) + (uint32_t)(wq + mrow) * (ASTRH * 2) + mcol;
    const uint32_t kB[2] = { smem_u32(smh + AK_OFF(0)) + (uint32_t)mrow * (ASTRH * 2) + mcol,
                             smem_u32(smh + AK_OFF(1)) + (uint32_t)mrow * (ASTRH * 2) + mcol };
    const uint32_t vB[2] = { smem_u32(smh + AV_OFF(0)) + (uint32_t)mrow * (ASTRH * 2) + mcol,
                             smem_u32(smh + AV_OFF(1)) + (uint32_t)mrow * (ASTRH * 2) + mcol };

    float oacc[8][4];
#pragma unroll
    for (int nt = 0; nt < 8; nt++)
#pragma unroll
        for (int r = 0; r < 4; r++) oacc[nt][r] = 0.f;
    float m0 = -INFINITY, m1 = -INFINITY, l0 = 0.f, l1 = 0.f;

    const int lr = lane >> 2;
    const int lc = (lane & 3) * 2;

    for (int kt = 0; kt < nkt; kt++) {
        const int buf = kt & 1;
        const int k0  = kt * 64;
        CP_WAIT0();
        __syncthreads();

        if (kt + 1 < nkt) {
            load_k(kt + 1, buf ^ 1);
            load_v(kt + 1, buf ^ 1);
            CP_COMMIT();
        }

        // ---- S = Q K^T : 4 ksteps x 4 p-tiles x 2 mmas = 32 mmas ----
        float sacc[8][4];
#pragma unroll
        for (int nt = 0; nt < 8; nt++)
#pragma unroll
            for (int r = 0; r < 4; r++) sacc[nt][r] = 0.f;

#pragma unroll
        for (int ks = 0; ks < 4; ks++) {
#pragma unroll
            for (int p = 0; p < 4; p++) {
                uint32_t kf[4];
                ldsm_x4(kf, kB[buf] + (uint32_t)(p * 16 * ASTRH * 2) + ks * 32);
                mma_f16(sacc[2 * p],     qfr[ks], kf[0], kf[2]);
                mma_f16(sacc[2 * p + 1], qfr[ks], kf[1], kf[3]);
            }
        }

        const int rg0 = q0 + wq + lr;
        if (kt >= 2 * qt) {
#pragma unroll
            for (int nt = 0; nt < 8; nt++) {
                int cb = k0 + nt * 8 + lc;
                if (cb     > rg0)     sacc[nt][0] = -1e30f;
                if (cb + 1 > rg0)     sacc[nt][1] = -1e30f;
                if (cb     > rg0 + 8) sacc[nt][2] = -1e30f;
                if (cb + 1 > rg0 + 8) sacc[nt][3] = -1e30f;
            }
        }

        // ---- online softmax (log2 domain) ----
        float mx0 = -1e30f, mx1 = -1e30f;
#pragma unroll
        for (int nt = 0; nt < 8; nt++) {
            mx0 = fmaxf(mx0, fmaxf(sacc[nt][0], sacc[nt][1]));
            mx1 = fmaxf(mx1, fmaxf(sacc[nt][2], sacc[nt][3]));
        }
        mx0 = fmaxf(mx0, __shfl_xor_sync(0xffffffffu, mx0, 1));
        mx0 = fmaxf(mx0, __shfl_xor_sync(0xffffffffu, mx0, 2));
        mx1 = fmaxf(mx1, __shfl_xor_sync(0xffffffffu, mx1, 1));
        mx1 = fmaxf(mx1, __shfl_xor_sync(0xffffffffu, mx1, 2));
        float mn0 = fmaxf(m0, mx0), mn1 = fmaxf(m1, mx1);
        float a0 = ex2(m0 - mn0), a1 = ex2(m1 - mn1);
        float rs0 = 0.f, rs1 = 0.f;
#pragma unroll
        for (int nt = 0; nt < 8; nt++) {
            float e0 = ex2(sacc[nt][0] - mn0);
            float e1 = ex2(sacc[nt][1] - mn0);
            float e2 = ex2(sacc[nt][2] - mn1);
            float e3 = ex2(sacc[nt][3] - mn1);
            sacc[nt][0] = e0; sacc[nt][1] = e1; sacc[nt][2] = e2; sacc[nt][3] = e3;
            rs0 += e0 + e1; rs1 += e2 + e3;
        }
        rs0 += __shfl_xor_sync(0xffffffffu, rs0, 1);
        rs0 += __shfl_xor_sync(0xffffffffu, rs0, 2);
        rs1 += __shfl_xor_sync(0xffffffffu, rs1, 1);
        rs1 += __shfl_xor_sync(0xffffffffu, rs1, 2);
        l0 = l0 * a0 + rs0; m0 = mn0;
        l1 = l1 * a1 + rs1; m1 = mn1;
#pragma unroll
        for (int nt = 0; nt < 8; nt++) {
            oacc[nt][0] *= a0; oacc[nt][1] *= a0;
            oacc[nt][2] *= a1; oacc[nt][3] *= a1;
        }

        // ---- stash P as fp16 (warp-local rows) ----
        {
            __half* pr0 = Ps + (wq + lr) * ASTRH + lc;
            __half* pr1 = pr0 + 8 * ASTRH;
#pragma unroll
            for (int nt = 0; nt < 8; nt++) {
                *reinterpret_cast<__half2*>(pr0 + nt * 8)
                    = __floats2half2_rn(sacc[nt][0], sacc[nt][1]);
                *reinterpret_cast<__half2*>(pr1 + nt * 8)
                    = __floats2half2_rn(sacc[nt][2], sacc[nt][3]);
            }
        }
        __syncwarp();

        // ---- O += P V : 4 ksteps x 4 d-tiles x 2 mmas = 32 mmas ----
#pragma unroll
        for (int ks = 0; ks < 4; ks++) {
            uint32_t pf[4];
            ldsm_x4(pf, pLd + ks * 32);
#pragma unroll
            for (int p = 0; p < 4; p++) {
                uint32_t vf[4];
                ldsm_x4(vf, vB[buf] + (uint32_t)(p * 16 * ASTRH * 2) + ks * 32);
                mma_f16(oacc[2 * p],     pf, vf[0], vf[2]);
                mma_f16(oacc[2 * p + 1], pf, vf[1], vf[3]);
            }
        }
    }

    // ---- epilogue: fp16 ctx ----
    const float i0 = 1.f / l0, i1 = 1.f / l1;
    const int row0 = q0 + wq + lr;
    __half* Ob = O + (size_t)(b * SEQ + row0) * D_MODEL + (size_t)h * DH + lc;
#pragma unroll
    for (int nt = 0; nt < 8; nt++) {
        *reinterpret_cast<__half2*>(Ob + nt * 8)
            = __floats2half2_rn(oacc[nt][0] * i0, oacc[nt][1] * i0);
        *reinterpret_cast<__half2*>(Ob + 8 * D_MODEL + nt * 8)
            = __floats2half2_rn(oacc[nt][2] * i1, oacc[nt][3] * i1);
    }
}

// ---------------------------------------------------------------------------
extern "C" void kernel_launch(void* const* d_in, const int* in_sizes, int n_in,
                              void* d_out, int out_size)
{
    const float* x  = (const float*)d_in[0];
    const float* Wq = (const float*)d_in[1];
    const float* Wk = (const float*)d_in[2];
    const float* Wv = (const float*)d_in[3];
    const float* Wo = (const float*)d_in[4];
    float* out = (float*)d_out;

    __half *xh, *wqh, *wkh, *wvh, *woh, *q16, *k16, *vt16, *ctx;
    cudaGetSymbolAddress((void**)&xh,   g_xh);
    cudaGetSymbolAddress((void**)&wqh,  g_wqh);
    cudaGetSymbolAddress((void**)&wkh,  g_wkh);
    cudaGetSymbolAddress((void**)&wvh,  g_wvh);
    cudaGetSymbolAddress((void**)&woh,  g_woh);
    cudaGetSymbolAddress((void**)&q16,  g_q16);
    cudaGetSymbolAddress((void**)&k16,  g_k16);
    cudaGetSymbolAddress((void**)&vt16, g_vt16);
    cudaGetSymbolAddress((void**)&ctx,  g_ctx);

    cudaFuncSetAttribute(hgemm<0>, cudaFuncAttributeMaxDynamicSharedMemorySize, GSMEM_BYTES);
    cudaFuncSetAttribute(hgemm<1>, cudaFuncAttributeMaxDynamicSharedMemorySize, GSMEM_BYTES);
    cudaFuncSetAttribute(hgemm<2>, cudaFuncAttributeMaxDynamicSharedMemorySize, GSMEM_BYTES);
    cudaFuncSetAttribute(attn_mma, cudaFuncAttributeMaxDynamicSharedMemorySize, AT_BYTES);

    // fp32 -> fp16 conversions
    const int NX = NTOK * D_MODEL, NW = D_MODEL * D_MODEL;
    f2h<<<NX / 1024, 256>>>(x,  xh,  NX);
    f2h<<<NW / 1024, 256>>>(Wq, wqh, NW);
    f2h<<<NW / 1024, 256>>>(Wk, wkh, NW);
    f2h<<<NW / 1024, 256>>>(Wv, wvh, NW);
    f2h<<<NW / 1024, 256>>>(Wo, woh, NW);

    dim3 gg (D_MODEL / BN, NTOK / BM);   // (8, 32)  — token-major outputs
    dim3 ggT(NTOK / BN, D_MODEL / BM);   // (32, 8)  — V^T output

    hgemm<1><<<gg,  256, GSMEM_BYTES>>>(xh,  wqh, (void*)q16,  NTOK,    D_MODEL, D_MODEL);
    hgemm<2><<<gg,  256, GSMEM_BYTES>>>(xh,  wkh, (void*)k16,  NTOK,    D_MODEL, D_MODEL);
    hgemm<2><<<ggT, 256, GSMEM_BYTES>>>(wvh, xh,  (void*)vt16, D_MODEL, NTOK,    D_MODEL);

    attn_mma<<<dim3(SEQ / 128, NH, BATCH), 256, AT_BYTES>>>(q16, k16, vt16, ctx);

    hgemm<0><<<gg, 256, GSMEM_BYTES>>>(ctx, woh, (void*)out, NTOK, D_MODEL, D_MODEL);
}